// round 1
// baseline (speedup 1.0000x reference)
#include <cuda_runtime.h>
#include <math.h>

#define B_  4
#define S_  1000
#define D_  512
#define H_  8
#define L_  4
#define V_  32000
#define HD_ 64
#define FF_ 2048
#define M_  (B_*S_)   // 4000 token rows

// ---------------- scratch (device globals; no allocations allowed) ----------
__device__ float g_x[M_*D_];
__device__ float g_q[M_*D_];
__device__ float g_k[M_*D_];
__device__ float g_v[M_*D_];
__device__ float g_c[M_*D_];
__device__ float g_t[M_*D_];
__device__ float g_h[M_*FF_];
__device__ float g_s[B_*H_*S_*S_];   // 128 MB attention scores

// ---------------- embedding + sinusoidal positional encoding ----------------
__global__ void embed_kernel(const int* __restrict__ tokens,
                             const float* __restrict__ emb,
                             float* __restrict__ x)
{
    int row = blockIdx.x;          // 0..3999  (= b*S + s)
    int d   = threadIdx.x;         // 0..511
    int s   = row % S_;
    int tok = tokens[row];
    int i   = d >> 1;
    // div = exp(-(2i) * ln(10000)/D)
    float dv  = expf(-(float)(2*i) * (9.210340371976184f / (float)D_));
    float arg = (float)s * dv;
    float pe  = (d & 1) ? cosf(arg) : sinf(arg);
    x[(long long)row*D_ + d] = emb[(long long)tok*D_ + d] + pe;
}

// ---------------- generic batched SGEMM -------------------------------------
// C[M,N] = act(alpha * A[M,K] @ B[K,N] + bias)
// TRB=true: B is accessed transposed, element (k,n) = B[n*ldb + k]  (for Q*K^T)
// Batch via blockIdx.z: b = z/H_, h = z%H_, pointer offsets b*s?b + h*s?h.
template<int BM,int BN,int BK,int TM,int TN,bool TRB>
__global__ __launch_bounds__(256,2)
void sgemm_kernel(const float* __restrict__ Ag, const float* __restrict__ Bg,
                  const float* __restrict__ bias, float* __restrict__ Cg,
                  int M, int N, int K,
                  int lda, int ldb, int ldc,
                  long long sAb, long long sAh,
                  long long sBb, long long sBh,
                  long long sCb, long long sCh,
                  float alpha, int relu)
{
    static_assert(BK == 16, "loader assumes BK==16");
    const int zb = blockIdx.z / H_;
    const int zh = blockIdx.z % H_;
    const float* A  = Ag + zb*sAb + zh*sAh;
    const float* Bp = Bg + zb*sBb + zh*sBh;
    float*       C  = Cg + zb*sCb + zh*sCh;

    __shared__ float As[BK][BM+4];
    __shared__ float Bs[BK][BN+4];

    const int tid = threadIdx.x;
    const int m0  = blockIdx.y * BM;
    const int n0  = blockIdx.x * BN;

    constexpr int TX = BN / TN;       // threads along N
    const int tx = tid % TX;
    const int ty = tid / TX;

    float acc[TM][TN];
    #pragma unroll
    for (int i=0;i<TM;i++)
        #pragma unroll
        for (int j=0;j<TN;j++) acc[i][j] = 0.f;

    // A loader: BMxBK, float4 along K, transposed store
    const int aRow = tid >> 2;            // 0..63
    const int aCol = (tid & 3) << 2;      // {0,4,8,12}
    // B loader (non-trans): BKxBN, float4 along N
    const int bRow = TRB ? (tid >> 2) : (tid / (BN/4));
    const int bCol = TRB ? ((tid & 3) << 2) : ((tid % (BN/4)) << 2);

    const int ktiles = (K + BK - 1) / BK;
    for (int kt = 0; kt < ktiles; kt++) {
        const int k0 = kt * BK;

        #pragma unroll
        for (int c = 0; c < (BM*BK)/1024; c++) {
            int r  = aRow + c*64;
            int gr = m0 + r, gc = k0 + aCol;
            float4 v4 = make_float4(0.f,0.f,0.f,0.f);
            if (gr < M && gc < K)
                v4 = *reinterpret_cast<const float4*>(A + (long long)gr*lda + gc);
            As[aCol+0][r]=v4.x; As[aCol+1][r]=v4.y; As[aCol+2][r]=v4.z; As[aCol+3][r]=v4.w;
        }
        if (!TRB) {
            #pragma unroll
            for (int c = 0; c < (BK*BN)/1024; c++) {
                int r  = bRow + c*(1024/BN);
                int gr = k0 + r, gc = n0 + bCol;
                float4 v4 = make_float4(0.f,0.f,0.f,0.f);
                if (gr < K && gc < N)
                    v4 = *reinterpret_cast<const float4*>(Bp + (long long)gr*ldb + gc);
                *reinterpret_cast<float4*>(&Bs[r][bCol]) = v4;
            }
        } else {
            #pragma unroll
            for (int c = 0; c < (BK*BN)/1024; c++) {
                int j  = bRow + c*64;             // column (N) index in tile
                int gj = n0 + j, gk = k0 + bCol;
                float4 v4 = make_float4(0.f,0.f,0.f,0.f);
                if (gj < N && gk < K)
                    v4 = *reinterpret_cast<const float4*>(Bp + (long long)gj*ldb + gk);
                Bs[bCol+0][j]=v4.x; Bs[bCol+1][j]=v4.y; Bs[bCol+2][j]=v4.z; Bs[bCol+3][j]=v4.w;
            }
        }
        __syncthreads();

        #pragma unroll
        for (int kk = 0; kk < BK; kk++) {
            float ra[TM], rb[TN];
            #pragma unroll
            for (int i = 0; i < TM/2; i++) {
                ra[i]       = As[kk][ty*(TM/2)+i];
                ra[i+TM/2]  = As[kk][BM/2 + ty*(TM/2)+i];
            }
            #pragma unroll
            for (int j = 0; j < TN/2; j++) {
                rb[j]       = Bs[kk][tx*(TN/2)+j];
                rb[j+TN/2]  = Bs[kk][BN/2 + tx*(TN/2)+j];
            }
            #pragma unroll
            for (int i = 0; i < TM; i++)
                #pragma unroll
                for (int j = 0; j < TN; j++)
                    acc[i][j] = fmaf(ra[i], rb[j], acc[i][j]);
        }
        __syncthreads();
    }

    // store (vectorized, N is always a multiple of 4 in this problem)
    #pragma unroll
    for (int i = 0; i < TM; i++) {
        int r = m0 + ((i < TM/2) ? (ty*(TM/2)+i) : (BM/2 + ty*(TM/2) + (i-TM/2)));
        if (r >= M) continue;
        float* crow = C + (long long)r*ldc;
        #pragma unroll
        for (int grp = 0; grp < 2; grp++) {
            int c0 = n0 + grp*(BN/2) + tx*(TN/2);
            if (c0 >= N) continue;
            float vals[TN/2];
            #pragma unroll
            for (int j = 0; j < TN/2; j++) {
                float vv = alpha * acc[i][grp*(TN/2)+j];
                if (bias) vv += bias[c0+j];
                if (relu) vv = fmaxf(vv, 0.f);
                vals[j] = vv;
            }
            if constexpr (TN/2 == 4) {
                *reinterpret_cast<float4*>(crow + c0) =
                    make_float4(vals[0],vals[1],vals[2],vals[3]);
            } else {
                *reinterpret_cast<float2*>(crow + c0) =
                    make_float2(vals[0],vals[1]);
            }
        }
    }
}

// ---------------- row softmax (in place) -------------------------------------
__global__ void softmax_kernel(float* __restrict__ data, int n, long long ld)
{
    float* p = data + (long long)blockIdx.x * ld;
    const int tid  = threadIdx.x;
    const int lane = tid & 31;
    const int wrp  = tid >> 5;
    __shared__ float buf[8];
    __shared__ float s_max, s_inv;

    float m = -3.4e38f;
    for (int i = tid; i < n; i += 256) m = fmaxf(m, p[i]);
    #pragma unroll
    for (int o = 16; o; o >>= 1) m = fmaxf(m, __shfl_xor_sync(0xffffffffu, m, o));
    if (lane == 0) buf[wrp] = m;
    __syncthreads();
    if (tid == 0) {
        float t = buf[0];
        #pragma unroll
        for (int i = 1; i < 8; i++) t = fmaxf(t, buf[i]);
        s_max = t;
    }
    __syncthreads();
    m = s_max;

    float s = 0.f;
    for (int i = tid; i < n; i += 256) {
        float e = __expf(p[i] - m);
        p[i] = e;
        s += e;
    }
    #pragma unroll
    for (int o = 16; o; o >>= 1) s += __shfl_xor_sync(0xffffffffu, s, o);
    if (lane == 0) buf[wrp] = s;
    __syncthreads();
    if (tid == 0) {
        float t = 0.f;
        #pragma unroll
        for (int i = 0; i < 8; i++) t += buf[i];
        s_inv = 1.0f / t;
    }
    __syncthreads();
    float inv = s_inv;
    for (int i = tid; i < n; i += 256) p[i] *= inv;
}

// ---------------- residual add + LayerNorm ----------------------------------
__global__ void add_ln_kernel(const float* __restrict__ xin,
                              const float* __restrict__ res,
                              const float* __restrict__ g,
                              const float* __restrict__ b,
                              float* __restrict__ xout)
{
    const int row = blockIdx.x;
    const int d   = threadIdx.x;           // 512 threads
    const int lane = d & 31;
    const int wrp  = d >> 5;                // 0..15
    long long idx = (long long)row*D_ + d;
    float y = xin[idx] + res[idx];

    __shared__ float bs[16], bq[16];
    __shared__ float s_mu, s_rs;
    float s1 = y, s2 = y*y;
    #pragma unroll
    for (int o = 16; o; o >>= 1) {
        s1 += __shfl_xor_sync(0xffffffffu, s1, o);
        s2 += __shfl_xor_sync(0xffffffffu, s2, o);
    }
    if (lane == 0) { bs[wrp] = s1; bq[wrp] = s2; }
    __syncthreads();
    if (d == 0) {
        float a = 0.f, c = 0.f;
        #pragma unroll
        for (int i = 0; i < 16; i++) { a += bs[i]; c += bq[i]; }
        float mu  = a * (1.0f/D_);
        float var = c * (1.0f/D_) - mu*mu;
        s_mu = mu;
        s_rs = rsqrtf(var + 1e-5f);
    }
    __syncthreads();
    xout[idx] = (y - s_mu) * s_rs * g[d] + b[d];
}

// ---------------- launcher ----------------------------------------------------
extern "C" void kernel_launch(void* const* d_in, const int* in_sizes, int n_in,
                              void* d_out, int out_size)
{
    (void)in_sizes; (void)n_in; (void)out_size;
    const int*   tokens = (const int*)  d_in[0];
    const float* emb  = (const float*)d_in[1];
    const float* wq   = (const float*)d_in[2];
    const float* bq   = (const float*)d_in[3];
    const float* wk   = (const float*)d_in[4];
    const float* bk   = (const float*)d_in[5];
    const float* wv   = (const float*)d_in[6];
    const float* bv   = (const float*)d_in[7];
    const float* wo   = (const float*)d_in[8];
    const float* bo   = (const float*)d_in[9];
    const float* ln1g = (const float*)d_in[10];
    const float* ln1b = (const float*)d_in[11];
    const float* w1   = (const float*)d_in[12];
    const float* b1   = (const float*)d_in[13];
    const float* w2   = (const float*)d_in[14];
    const float* b2   = (const float*)d_in[15];
    const float* ln2g = (const float*)d_in[16];
    const float* ln2b = (const float*)d_in[17];
    const float* fcw  = (const float*)d_in[18];
    const float* fcb  = (const float*)d_in[19];
    float* out = (float*)d_out;

    float *x,*q,*k,*v,*cx,*t,*hb,*sc;
    cudaGetSymbolAddress((void**)&x,  g_x);
    cudaGetSymbolAddress((void**)&q,  g_q);
    cudaGetSymbolAddress((void**)&k,  g_k);
    cudaGetSymbolAddress((void**)&v,  g_v);
    cudaGetSymbolAddress((void**)&cx, g_c);
    cudaGetSymbolAddress((void**)&t,  g_t);
    cudaGetSymbolAddress((void**)&hb, g_h);
    cudaGetSymbolAddress((void**)&sc, g_s);

    embed_kernel<<<M_, D_>>>(tokens, emb, x);

    const dim3 gw (D_/128,  (M_+127)/128, 1);   // [4000 x 512]
    const dim3 g1 (FF_/128, (M_+127)/128, 1);   // [4000 x 2048]
    const dim3 gsc((S_+127)/128, (S_+127)/128, B_*H_);
    const dim3 gcx(1, (S_+127)/128, B_*H_);

    for (int l = 0; l < L_; l++) {
        const float* lwq = wq + (long long)l*D_*D_;
        const float* lwk = wk + (long long)l*D_*D_;
        const float* lwv = wv + (long long)l*D_*D_;
        const float* lwo = wo + (long long)l*D_*D_;
        const float* lw1 = w1 + (long long)l*D_*FF_;
        const float* lw2 = w2 + (long long)l*FF_*D_;

        // Q, K, V projections
        sgemm_kernel<128,128,16,8,8,false><<<gw,256>>>(x, lwq, bq + l*D_, q,
            M_, D_, D_, D_, D_, D_, 0,0,0,0,0,0, 1.f, 0);
        sgemm_kernel<128,128,16,8,8,false><<<gw,256>>>(x, lwk, bk + l*D_, k,
            M_, D_, D_, D_, D_, D_, 0,0,0,0,0,0, 1.f, 0);
        sgemm_kernel<128,128,16,8,8,false><<<gw,256>>>(x, lwv, bv + l*D_, v,
            M_, D_, D_, D_, D_, D_, 0,0,0,0,0,0, 1.f, 0);

        // scores[b,h] = (Q_h @ K_h^T) / 8      [S x S], K=64
        sgemm_kernel<128,128,16,8,8,true><<<gsc,256>>>(q, k, nullptr, sc,
            S_, S_, HD_, D_, D_, S_,
            (long long)S_*D_, HD_,
            (long long)S_*D_, HD_,
            (long long)H_*S_*S_, (long long)S_*S_, 0.125f, 0);

        softmax_kernel<<<B_*H_*S_, 256>>>(sc, S_, S_);

        // ctx[b,h] = attn @ V_h                [S x 64], K=S
        sgemm_kernel<128,64,16,8,4,false><<<gcx,256>>>(sc, v, nullptr, cx,
            S_, HD_, S_, S_, D_, D_,
            (long long)H_*S_*S_, (long long)S_*S_,
            (long long)S_*D_, HD_,
            (long long)S_*D_, HD_, 1.f, 0);

        // output projection
        sgemm_kernel<128,128,16,8,8,false><<<gw,256>>>(cx, lwo, bo + l*D_, t,
            M_, D_, D_, D_, D_, D_, 0,0,0,0,0,0, 1.f, 0);

        add_ln_kernel<<<M_, D_>>>(x, t, ln1g + l*D_, ln1b + l*D_, x);

        // FFN
        sgemm_kernel<128,128,16,8,8,false><<<g1,256>>>(x, lw1, b1 + l*FF_, hb,
            M_, FF_, D_, D_, FF_, FF_, 0,0,0,0,0,0, 1.f, 1);
        sgemm_kernel<128,128,16,8,8,false><<<gw,256>>>(hb, lw2, b2 + l*D_, t,
            M_, D_, FF_, FF_, D_, D_, 0,0,0,0,0,0, 1.f, 0);

        add_ln_kernel<<<M_, D_>>>(x, t, ln2g + l*D_, ln2b + l*D_, x);
    }

    // logits -> d_out, then row softmax over V
    const dim3 gl(V_/128, (M_+127)/128, 1);
    sgemm_kernel<128,128,16,8,8,false><<<gl,256>>>(x, fcw, fcb, out,
        M_, V_, D_, D_, V_, V_, 0,0,0,0,0,0, 1.f, 0);
    softmax_kernel<<<M_, 256>>>(out, V_, V_);
}

// round 4
// speedup vs baseline: 1.6442x; 1.6442x over previous
#include <cuda_runtime.h>
#include <cuda_bf16.h>
#include <math.h>
#include <stdint.h>

#define B_  4
#define S_  1000
#define D_  512
#define H_  8
#define L_  4
#define V_  32000
#define HD_ 64
#define FF_ 2048
#define M_  (B_*S_)
#define SP_ 1024              // padded S for attn GEMM K-dim

// ======================= scratch (device globals) ===========================
__device__ __align__(128) float g_x[M_*D_];
__device__ __align__(128) float g_v[M_*D_];
__device__ __align__(128) float g_t[M_*D_];
__device__ __align__(128) float g_s[B_*H_*S_*S_];                 // scores fp32
__device__ __align__(128) __nv_bfloat16 g_ah[M_*D_],  g_al[M_*D_];
__device__ __align__(128) __nv_bfloat16 g_hh[M_*FF_], g_hl[M_*FF_];
__device__ __align__(128) __nv_bfloat16 g_qh[M_*D_],  g_ql[M_*D_];
__device__ __align__(128) __nv_bfloat16 g_kh[M_*D_],  g_kl[M_*D_];
__device__ __align__(128) __nv_bfloat16 g_bh[(size_t)V_*D_], g_bl[(size_t)V_*D_];
__device__ __align__(128) __nv_bfloat16 g_sh[(size_t)B_*H_*S_*SP_], g_sl[(size_t)B_*H_*S_*SP_];
__device__ __align__(128) __nv_bfloat16 g_vh[(size_t)B_*H_*HD_*SP_], g_vl[(size_t)B_*H_*HD_*SP_];

// ======================= helpers =============================================
__device__ __forceinline__ uint32_t smem_u32(const void* p){
    uint32_t a;
    asm("{ .reg .u64 t; cvta.to.shared.u64 t, %1; cvt.u32.u64 %0, t; }" : "=r"(a) : "l"(p));
    return a;
}
__device__ __forceinline__ void split1(float v, __nv_bfloat16& h, __nv_bfloat16& l){
    h = __float2bfloat16(v);
    l = __float2bfloat16(v - __bfloat162float(h));
}
__device__ __forceinline__ void ldm_x4(uint32_t* r, uint32_t addr){
    asm volatile("ldmatrix.sync.aligned.m8n8.x4.shared.b16 {%0,%1,%2,%3}, [%4];"
        : "=r"(r[0]), "=r"(r[1]), "=r"(r[2]), "=r"(r[3]) : "r"(addr));
}
#define MMA16816(c, a, b0v, b1v) \
    asm volatile("mma.sync.aligned.m16n8k16.row.col.f32.bf16.bf16.f32 " \
        "{%0,%1,%2,%3}, {%4,%5,%6,%7}, {%8,%9}, {%0,%1,%2,%3};" \
        : "+f"((c)[0]), "+f"((c)[1]), "+f"((c)[2]), "+f"((c)[3]) \
        : "r"((a)[0]), "r"((a)[1]), "r"((a)[2]), "r"((a)[3]), "r"(b0v), "r"(b1v))

// ======================= smem tile layout ====================================
// row stride 40 bf16 = 80 B (16B-aligned rows, conflict-free ldmatrix)
#define SROW_B   80
#define MAT_B    (128*SROW_B)       // 10240 B per matrix tile
#define STG_B    (4*MAT_B)          // Ah,Al,Bh,Bl per stage
#define TMM_SMEM (2*STG_B)          // 81920 B

// gmem bf16 -> padded smem tile (128 rows x 32 bf16)
__device__ __forceinline__ void ld_tile(const __nv_bfloat16* __restrict__ g, int ld,
                                        int row0, int rowmax, int k0,
                                        char* dst, int tid)
{
#pragma unroll
    for (int c = 0; c < 2; c++) {
        int idx = tid + c*256;          // 0..511
        int r = idx >> 2;               // 0..127
        int q = idx & 3;                // 16B quarter
        uint4 v = make_uint4(0u,0u,0u,0u);
        int gr = row0 + r;
        if (gr < rowmax)
            v = *reinterpret_cast<const uint4*>(g + (size_t)gr*ld + k0 + q*8);
        *reinterpret_cast<uint4*>(dst + r*SROW_B + q*16) = v;
    }
}

// ======================= split-bf16 mma.sync GEMM ============================
// out = relu(alpha * (Ah+Al)[M,K] @ (Bh+Bl)[Nv,K]^T + bias)
// outmode 0: fp32 C ; outmode 1: bf16 hi/lo split into Oh/Ol
__global__ __launch_bounds__(256, 1)
void tmm_kernel(const __nv_bfloat16* __restrict__ Ah, const __nv_bfloat16* __restrict__ Al, int lda,
                const __nv_bfloat16* __restrict__ Bh, const __nv_bfloat16* __restrict__ Bl, int ldb,
                const float* __restrict__ bias,
                float* __restrict__ C,
                __nv_bfloat16* __restrict__ Oh, __nv_bfloat16* __restrict__ Ol, int ldc,
                int Mv, int Nv, int K,
                long long sAb, long long sAh, long long sBb, long long sBh,
                long long sCb, long long sCh,
                float alpha, int relu, int outmode)
{
    extern __shared__ char sm[];
    const uint32_t sb = smem_u32(sm);
    const int tid  = threadIdx.x;
    const int wid  = tid >> 5;
    const int lane = tid & 31;

    const long long zb = blockIdx.z / H_;
    const long long zh = blockIdx.z % H_;
    Ah += zb*sAb + zh*sAh;  Al += zb*sAb + zh*sAh;
    Bh += zb*sBb + zh*sBh;  Bl += zb*sBb + zh*sBh;
    const size_t cOff = (size_t)(zb*sCb + zh*sCh);

    const int m0 = blockIdx.y * 128;
    const int n0 = blockIdx.x * 128;

    // warp tile: 2(m) x 4(n) warps -> 64x32 each
    const int wm = (wid >> 2) * 64;
    const int wn = (wid & 3) * 32;

    // per-lane ldmatrix offsets (bytes, within a matrix tile)
    const uint32_t aoff = (uint32_t)(wm + (lane & 15)) * SROW_B + ((lane >> 4) * 16);
    const uint32_t boff = (uint32_t)(wn + (lane & 7) + ((lane >> 4) * 8)) * SROW_B
                        + (((lane >> 3) & 1) * 16);

    float acc[4][4][4];
#pragma unroll
    for (int i = 0; i < 4; i++)
#pragma unroll
        for (int j = 0; j < 4; j++)
#pragma unroll
            for (int e = 0; e < 4; e++) acc[i][j][e] = 0.f;

    const int NC = K >> 5;                     // BK = 32
    ld_tile(Ah, lda, m0, Mv, 0, sm + 0*MAT_B, tid);
    ld_tile(Al, lda, m0, Mv, 0, sm + 1*MAT_B, tid);
    ld_tile(Bh, ldb, n0, Nv, 0, sm + 2*MAT_B, tid);
    ld_tile(Bl, ldb, n0, Nv, 0, sm + 3*MAT_B, tid);
    __syncthreads();

    for (int kc = 0; kc < NC; kc++) {
        const int s = kc & 1;
        if (kc + 1 < NC) {
            const int ns = (kc + 1) & 1;
            const int k0 = (kc + 1) << 5;
            ld_tile(Ah, lda, m0, Mv, k0, sm + ns*STG_B + 0*MAT_B, tid);
            ld_tile(Al, lda, m0, Mv, k0, sm + ns*STG_B + 1*MAT_B, tid);
            ld_tile(Bh, ldb, n0, Nv, k0, sm + ns*STG_B + 2*MAT_B, tid);
            ld_tile(Bl, ldb, n0, Nv, k0, sm + ns*STG_B + 3*MAT_B, tid);
        }
        const uint32_t aBH = sb + s*STG_B + 0*MAT_B + aoff;
        const uint32_t aBL = sb + s*STG_B + 1*MAT_B + aoff;
        const uint32_t bBH = sb + s*STG_B + 2*MAT_B + boff;
        const uint32_t bBL = sb + s*STG_B + 3*MAT_B + boff;

#pragma unroll
        for (int ks = 0; ks < 2; ks++) {
            uint32_t ah[4][4], al[4][4], bh[2][4], bl[2][4];
#pragma unroll
            for (int mt = 0; mt < 4; mt++) {
                ldm_x4(ah[mt], aBH + mt*(16*SROW_B) + ks*32);
                ldm_x4(al[mt], aBL + mt*(16*SROW_B) + ks*32);
            }
#pragma unroll
            for (int p = 0; p < 2; p++) {
                ldm_x4(bh[p], bBH + p*(16*SROW_B) + ks*32);
                ldm_x4(bl[p], bBL + p*(16*SROW_B) + ks*32);
            }
#pragma unroll
            for (int mt = 0; mt < 4; mt++)
#pragma unroll
                for (int nt = 0; nt < 4; nt++) {
                    uint32_t b0h = bh[nt>>1][(nt&1)*2], b1h = bh[nt>>1][(nt&1)*2+1];
                    uint32_t b0l = bl[nt>>1][(nt&1)*2], b1l = bl[nt>>1][(nt&1)*2+1];
                    MMA16816(acc[mt][nt], ah[mt], b0h, b1h);
                    MMA16816(acc[mt][nt], ah[mt], b0l, b1l);
                    MMA16816(acc[mt][nt], al[mt], b0h, b1h);
                }
        }
        __syncthreads();
    }

    // ---- epilogue ----
    const int g  = lane >> 2;      // fragment row group
    const int tg = lane & 3;       // fragment col pair
#pragma unroll
    for (int mt = 0; mt < 4; mt++) {
#pragma unroll
        for (int half = 0; half < 2; half++) {
            int r = m0 + wm + mt*16 + g + half*8;
            if (r >= Mv) continue;
#pragma unroll
            for (int nt = 0; nt < 4; nt++) {
                int c0 = n0 + wn + nt*8 + tg*2;
                if (c0 >= Nv) continue;
                float v0 = alpha*acc[mt][nt][half*2+0];
                float v1 = alpha*acc[mt][nt][half*2+1];
                if (bias) { v0 += bias[c0]; v1 += bias[c0+1]; }
                if (relu) { v0 = fmaxf(v0, 0.f); v1 = fmaxf(v1, 0.f); }
                size_t base = cOff + (size_t)r*ldc + c0;
                if (outmode == 0) {
                    *reinterpret_cast<float2*>(C + base) = make_float2(v0, v1);
                } else {
                    __nv_bfloat16 h0,l0,h1,l1;
                    split1(v0,h0,l0); split1(v1,h1,l1);
                    *reinterpret_cast<__nv_bfloat162*>(Oh + base) = __nv_bfloat162(h0,h1);
                    *reinterpret_cast<__nv_bfloat162*>(Ol + base) = __nv_bfloat162(l0,l1);
                }
            }
        }
    }
}

// ======================= weight transpose + split ============================
__global__ void wsplit_t(const float* __restrict__ W,
                         __nv_bfloat16* __restrict__ oh,
                         __nv_bfloat16* __restrict__ ol, int K, int N)
{
    __shared__ float t[32][33];
    int n = blockIdx.x*32 + threadIdx.x;
    int k0 = blockIdx.y*32;
    #pragma unroll
    for (int j = 0; j < 4; j++)
        t[threadIdx.y + j*8][threadIdx.x] = W[(size_t)(k0 + threadIdx.y + j*8)*N + n];
    __syncthreads();
    int k = k0 + threadIdx.x;
    #pragma unroll
    for (int j = 0; j < 4; j++) {
        int nn = blockIdx.x*32 + threadIdx.y + j*8;
        __nv_bfloat16 h,l; split1(t[threadIdx.x][threadIdx.y + j*8], h, l);
        oh[(size_t)nn*K + k] = h;  ol[(size_t)nn*K + k] = l;
    }
}

// V [4000,512] fp32 -> V^T per head [32][64][1024] bf16 hi/lo (zero pad K)
__global__ void vt_split(const float* __restrict__ v,
                         __nv_bfloat16* __restrict__ oh,
                         __nv_bfloat16* __restrict__ ol)
{
    size_t idx = (size_t)blockIdx.x*256 + threadIdx.x;   // < 32*64*1024
    int z = (int)(idx >> 16);
    int n = (int)((idx >> 10) & 63);
    int k = (int)(idx & 1023);
    float val = (k < S_) ? v[((size_t)(z >> 3)*S_ + k)*D_ + (z & 7)*HD_ + n] : 0.f;
    __nv_bfloat16 h,l; split1(val, h, l); oh[idx]=h; ol[idx]=l;
}

// ======================= embed + posenc (+ split) ============================
__global__ void embed_kernel(const int* __restrict__ tokens,
                             const float* __restrict__ emb,
                             float* __restrict__ x,
                             __nv_bfloat16* __restrict__ oh,
                             __nv_bfloat16* __restrict__ ol)
{
    int row = blockIdx.x, d = threadIdx.x;
    int s = row % S_;
    int tok = tokens[row];
    int i = d >> 1;
    float dv  = expf(-(float)(2*i) * (9.210340371976184f / (float)D_));
    float arg = (float)s * dv;
    float pe  = (d & 1) ? cosf(arg) : sinf(arg);
    float val = emb[(size_t)tok*D_ + d] + pe;
    size_t idx = (size_t)row*D_ + d;
    x[idx] = val;
    __nv_bfloat16 h,l; split1(val, h, l); oh[idx]=h; ol[idx]=l;
}

// ======================= scores softmax + split + pad ========================
__global__ void softmax_split(const float* __restrict__ sc,
                              __nv_bfloat16* __restrict__ oh,
                              __nv_bfloat16* __restrict__ ol)
{
    __shared__ float row[S_];
    __shared__ float bm[8], bs[8];
    __shared__ float s_m, s_inv;
    int z = blockIdx.x / S_, r = blockIdx.x % S_;
    const float* p = sc + (size_t)z*S_*S_ + (size_t)r*S_;
    const int tid = threadIdx.x, lane = tid & 31, wrp = tid >> 5;

    float m = -3.4e38f;
    for (int i = tid; i < S_; i += 256) { float v = p[i]; row[i] = v; m = fmaxf(m, v); }
    #pragma unroll
    for (int o = 16; o; o >>= 1) m = fmaxf(m, __shfl_xor_sync(0xffffffffu, m, o));
    if (lane == 0) bm[wrp] = m;
    __syncthreads();
    if (tid == 0) {
        float t = bm[0];
        #pragma unroll
        for (int i = 1; i < 8; i++) t = fmaxf(t, bm[i]);
        s_m = t;
    }
    __syncthreads();
    m = s_m;
    float s = 0.f;
    for (int i = tid; i < S_; i += 256) s += __expf(row[i] - m);
    #pragma unroll
    for (int o = 16; o; o >>= 1) s += __shfl_xor_sync(0xffffffffu, s, o);
    if (lane == 0) bs[wrp] = s;
    __syncthreads();
    if (tid == 0) {
        float t = 0.f;
        #pragma unroll
        for (int i = 0; i < 8; i++) t += bs[i];
        s_inv = 1.0f / t;
    }
    __syncthreads();
    const float mm = s_m, inv = s_inv;
    const size_t ob = (size_t)z*S_*SP_ + (size_t)r*SP_;
    for (int c = tid; c < SP_; c += 256) {
        float e = (c < S_) ? __expf(row[c] - mm) * inv : 0.f;
        __nv_bfloat16 h,l; split1(e, h, l);
        oh[ob + c] = h;  ol[ob + c] = l;
    }
}

// ======================= final V-softmax (in place) ==========================
__global__ void softmax_kernel(float* __restrict__ data, int n, long long ld)
{
    float* p = data + (long long)blockIdx.x * ld;
    const int tid = threadIdx.x, lane = tid & 31, wrp = tid >> 5;
    __shared__ float bm[8], bs[8];
    __shared__ float s_m, s_inv;

    float m = -3.4e38f, s = 0.f;
    for (int i = tid; i < n; i += 256) {
        float v = p[i];
        float nm = fmaxf(m, v);
        s = s*__expf(m - nm) + __expf(v - nm);
        m = nm;
    }
    #pragma unroll
    for (int o = 16; o; o >>= 1) {
        float om = __shfl_xor_sync(0xffffffffu, m, o);
        float os = __shfl_xor_sync(0xffffffffu, s, o);
        float nm = fmaxf(m, om);
        s = s*__expf(m - nm) + os*__expf(om - nm);
        m = nm;
    }
    if (lane == 0) { bm[wrp] = m; bs[wrp] = s; }
    __syncthreads();
    if (tid == 0) {
        float tm = bm[0], ts = bs[0];
        #pragma unroll
        for (int i = 1; i < 8; i++) {
            float nm = fmaxf(tm, bm[i]);
            ts = ts*__expf(tm - nm) + bs[i]*__expf(bm[i] - nm);
            tm = nm;
        }
        s_m = tm; s_inv = 1.0f / ts;
    }
    __syncthreads();
    float mm = s_m, inv = s_inv;
    for (int i = tid; i < n; i += 256)
        p[i] = __expf(p[i] - mm) * inv;
}

// ======================= residual add + LayerNorm (+ split) ==================
__global__ void add_ln_kernel(const float* __restrict__ xin,
                              const float* __restrict__ res,
                              const float* __restrict__ g,
                              const float* __restrict__ b,
                              float* __restrict__ xout,
                              __nv_bfloat16* __restrict__ oh,
                              __nv_bfloat16* __restrict__ ol)
{
    const int row = blockIdx.x, d = threadIdx.x;
    const int lane = d & 31, wrp = d >> 5;
    size_t idx = (size_t)row*D_ + d;
    float y = xin[idx] + res[idx];
    __shared__ float bsum[16], bsq[16];
    __shared__ float s_mu, s_rs;
    float s1 = y, s2 = y*y;
    #pragma unroll
    for (int o = 16; o; o >>= 1) {
        s1 += __shfl_xor_sync(0xffffffffu, s1, o);
        s2 += __shfl_xor_sync(0xffffffffu, s2, o);
    }
    if (lane == 0) { bsum[wrp] = s1; bsq[wrp] = s2; }
    __syncthreads();
    if (d == 0) {
        float a = 0.f, c = 0.f;
        #pragma unroll
        for (int i = 0; i < 16; i++) { a += bsum[i]; c += bsq[i]; }
        float mu = a * (1.0f/D_);
        float var = c * (1.0f/D_) - mu*mu;
        s_mu = mu; s_rs = rsqrtf(var + 1e-5f);
    }
    __syncthreads();
    float val = (y - s_mu) * s_rs * g[d] + b[d];
    xout[idx] = val;
    __nv_bfloat16 h,l; split1(val, h, l); oh[idx]=h; ol[idx]=l;
}

// ======================= launcher ============================================
extern "C" void kernel_launch(void* const* d_in, const int* in_sizes, int n_in,
                              void* d_out, int out_size)
{
    (void)in_sizes; (void)n_in; (void)out_size;
    const int*   tokens = (const int*)  d_in[0];
    const float* emb  = (const float*)d_in[1];
    const float* wq   = (const float*)d_in[2];
    const float* bq   = (const float*)d_in[3];
    const float* wk   = (const float*)d_in[4];
    const float* bk   = (const float*)d_in[5];
    const float* wv   = (const float*)d_in[6];
    const float* bv   = (const float*)d_in[7];
    const float* wo   = (const float*)d_in[8];
    const float* bo   = (const float*)d_in[9];
    const float* ln1g = (const float*)d_in[10];
    const float* ln1b = (const float*)d_in[11];
    const float* w1   = (const float*)d_in[12];
    const float* b1   = (const float*)d_in[13];
    const float* w2   = (const float*)d_in[14];
    const float* b2   = (const float*)d_in[15];
    const float* ln2g = (const float*)d_in[16];
    const float* ln2b = (const float*)d_in[17];
    const float* fcw  = (const float*)d_in[18];
    const float* fcb  = (const float*)d_in[19];
    float* out = (float*)d_out;

    float *x,*v,*t,*sc;
    __nv_bfloat16 *ah,*al,*hh,*hl,*qh,*ql,*kh,*kl,*bh,*bl,*sh,*sl,*vh,*vl;
    cudaGetSymbolAddress((void**)&x,  g_x);  cudaGetSymbolAddress((void**)&v,  g_v);
    cudaGetSymbolAddress((void**)&t,  g_t);  cudaGetSymbolAddress((void**)&sc, g_s);
    cudaGetSymbolAddress((void**)&ah, g_ah); cudaGetSymbolAddress((void**)&al, g_al);
    cudaGetSymbolAddress((void**)&hh, g_hh); cudaGetSymbolAddress((void**)&hl, g_hl);
    cudaGetSymbolAddress((void**)&qh, g_qh); cudaGetSymbolAddress((void**)&ql, g_ql);
    cudaGetSymbolAddress((void**)&kh, g_kh); cudaGetSymbolAddress((void**)&kl, g_kl);
    cudaGetSymbolAddress((void**)&bh, g_bh); cudaGetSymbolAddress((void**)&bl, g_bl);
    cudaGetSymbolAddress((void**)&sh, g_sh); cudaGetSymbolAddress((void**)&sl, g_sl);
    cudaGetSymbolAddress((void**)&vh, g_vh); cudaGetSymbolAddress((void**)&vl, g_vl);

    cudaFuncSetAttribute(tmm_kernel, cudaFuncAttributeMaxDynamicSharedMemorySize, TMM_SMEM);

    embed_kernel<<<M_, D_>>>(tokens, emb, x, ah, al);

    const dim3 gDD (D_/128,  (M_+127)/128);
    const dim3 gFF (FF_/128, (M_+127)/128);
    const dim3 gSC ((S_+127)/128, (S_+127)/128, B_*H_);
    const dim3 gCX (1, (S_+127)/128, B_*H_);
    const dim3 tb (32, 8);

    for (int l = 0; l < L_; l++) {
        const float* lwq = wq + (size_t)l*D_*D_;
        const float* lwk = wk + (size_t)l*D_*D_;
        const float* lwv = wv + (size_t)l*D_*D_;
        const float* lwo = wo + (size_t)l*D_*D_;
        const float* lw1 = w1 + (size_t)l*D_*FF_;
        const float* lw2 = w2 + (size_t)l*FF_*D_;

        // ---- QKV projections ----
        wsplit_t<<<dim3(D_/32, D_/32), tb>>>(lwq, bh, bl, D_, D_);
        tmm_kernel<<<gDD, 256, TMM_SMEM>>>(ah, al, D_, bh, bl, D_, bq + l*D_,
            nullptr, qh, ql, D_, M_, D_, D_, 0,0,0,0,0,0, 1.f, 0, 1);
        wsplit_t<<<dim3(D_/32, D_/32), tb>>>(lwk, bh, bl, D_, D_);
        tmm_kernel<<<gDD, 256, TMM_SMEM>>>(ah, al, D_, bh, bl, D_, bk + l*D_,
            nullptr, kh, kl, D_, M_, D_, D_, 0,0,0,0,0,0, 1.f, 0, 1);
        wsplit_t<<<dim3(D_/32, D_/32), tb>>>(lwv, bh, bl, D_, D_);
        tmm_kernel<<<gDD, 256, TMM_SMEM>>>(ah, al, D_, bh, bl, D_, bv + l*D_,
            v, nullptr, nullptr, D_, M_, D_, D_, 0,0,0,0,0,0, 1.f, 0, 0);

        // ---- scores = QK^T/8 (K=64) ----
        tmm_kernel<<<gSC, 256, TMM_SMEM>>>(qh, ql, D_, kh, kl, D_, nullptr,
            sc, nullptr, nullptr, S_, S_, S_, 64,
            (long long)S_*D_, HD_, (long long)S_*D_, HD_,
            (long long)H_*S_*S_, (long long)S_*S_, 0.125f, 0, 0);

        softmax_split<<<B_*H_*S_, 256>>>(sc, sh, sl);
        vt_split<<<(B_*H_*HD_*SP_)/256, 256>>>(v, vh, vl);

        // ---- ctx = attn @ V (K=1024 padded) -> split into ah/al ----
        tmm_kernel<<<gCX, 256, TMM_SMEM>>>(sh, sl, SP_, vh, vl, SP_, nullptr,
            nullptr, ah, al, D_, S_, HD_, SP_,
            (long long)H_*S_*SP_, (long long)S_*SP_,
            (long long)H_*HD_*SP_, (long long)HD_*SP_,
            (long long)S_*D_, HD_, 1.f, 0, 1);

        // ---- output projection ----
        wsplit_t<<<dim3(D_/32, D_/32), tb>>>(lwo, bh, bl, D_, D_);
        tmm_kernel<<<gDD, 256, TMM_SMEM>>>(ah, al, D_, bh, bl, D_, bo + l*D_,
            t, nullptr, nullptr, D_, M_, D_, D_, 0,0,0,0,0,0, 1.f, 0, 0);

        add_ln_kernel<<<M_, D_>>>(x, t, ln1g + l*D_, ln1b + l*D_, x, ah, al);

        // ---- FFN ----
        wsplit_t<<<dim3(FF_/32, D_/32), tb>>>(lw1, bh, bl, D_, FF_);
        tmm_kernel<<<gFF, 256, TMM_SMEM>>>(ah, al, D_, bh, bl, D_, b1 + l*FF_,
            nullptr, hh, hl, FF_, M_, FF_, D_, 0,0,0,0,0,0, 1.f, 1, 1);
        wsplit_t<<<dim3(D_/32, FF_/32), tb>>>(lw2, bh, bl, FF_, D_);
        tmm_kernel<<<gDD, 256, TMM_SMEM>>>(hh, hl, FF_, bh, bl, FF_, b2 + l*D_,
            t, nullptr, nullptr, D_, M_, D_, FF_, 0,0,0,0,0,0, 1.f, 0, 0);

        add_ln_kernel<<<M_, D_>>>(x, t, ln2g + l*D_, ln2b + l*D_, x, ah, al);
    }

    // ---- logits + softmax ----
    wsplit_t<<<dim3(V_/32, D_/32), tb>>>(fcw, bh, bl, D_, V_);
    tmm_kernel<<<dim3(V_/128, (M_+127)/128), 256, TMM_SMEM>>>(ah, al, D_, bh, bl, D_,
        fcb, out, nullptr, nullptr, V_, M_, V_, D_, 0,0,0,0,0,0, 1.f, 0, 0);
    softmax_kernel<<<M_, 256>>>(out, V_, V_);
}

// round 5
// speedup vs baseline: 2.2602x; 1.3747x over previous
#include <cuda_runtime.h>
#include <cuda_bf16.h>
#include <math.h>
#include <stdint.h>

#define B_  4
#define S_  1000
#define D_  512
#define H_  8
#define L_  4
#define V_  32000
#define HD_ 64
#define FF_ 2048
#define M_  (B_*S_)
#define SP_ 1024

// ======================= scratch (device globals, zero-init) =================
__device__ __align__(128) float g_x[M_*D_];
__device__ __align__(128) float g_t[M_*D_];
__device__ __align__(128) float g_s[B_*H_*S_*S_];                 // scores fp32
__device__ __align__(128) __nv_bfloat16 g_ah[M_*D_],  g_al[M_*D_];
__device__ __align__(128) __nv_bfloat16 g_hh[M_*FF_], g_hl[M_*FF_];
__device__ __align__(128) __nv_bfloat16 g_qh[M_*D_];
__device__ __align__(128) __nv_bfloat16 g_kh[M_*D_];
__device__ __align__(128) __nv_bfloat16 g_bh[(size_t)V_*D_], g_bl[(size_t)V_*D_];
__device__ __align__(128) __nv_bfloat16 g_sh[(size_t)B_*H_*S_*SP_];   // probs (pad stays 0)
__device__ __align__(128) __nv_bfloat16 g_vh[(size_t)B_*H_*HD_*SP_];  // V^T (pad stays 0)

// ======================= helpers =============================================
__device__ __forceinline__ uint32_t smem_u32(const void* p){
    uint32_t a;
    asm("{ .reg .u64 t; cvta.to.shared.u64 t, %1; cvt.u32.u64 %0, t; }" : "=r"(a) : "l"(p));
    return a;
}
__device__ __forceinline__ void split1(float v, __nv_bfloat16& h, __nv_bfloat16& l){
    h = __float2bfloat16(v);
    l = __float2bfloat16(v - __bfloat162float(h));
}
__device__ __forceinline__ void ldm_x4(uint32_t* r, uint32_t addr){
    asm volatile("ldmatrix.sync.aligned.m8n8.x4.shared.b16 {%0,%1,%2,%3}, [%4];"
        : "=r"(r[0]), "=r"(r[1]), "=r"(r[2]), "=r"(r[3]) : "r"(addr));
}
#define MMA16816(c, a, b0v, b1v) \
    asm volatile("mma.sync.aligned.m16n8k16.row.col.f32.bf16.bf16.f32 " \
        "{%0,%1,%2,%3}, {%4,%5,%6,%7}, {%8,%9}, {%0,%1,%2,%3};" \
        : "+f"((c)[0]), "+f"((c)[1]), "+f"((c)[2]), "+f"((c)[3]) \
        : "r"((a)[0]), "r"((a)[1]), "r"((a)[2]), "r"((a)[3]), "r"(b0v), "r"(b1v))
#define CP_COMMIT() asm volatile("cp.async.commit_group;" ::: "memory")
#define CP_WAIT2()  asm volatile("cp.async.wait_group 2;" ::: "memory")

// ======================= smem tile layout ====================================
#define SROW_B   80                 // 80 B row stride (16B aligned, conflict-free)
#define MAT_B    (128*SROW_B)       // 10240 B per 128x32 bf16 tile
#define NSTG     4

// async gmem bf16 -> padded smem tile (128 rows x 32 bf16), zero-fill OOB rows
__device__ __forceinline__ void cp_tile(const __nv_bfloat16* __restrict__ g, int ld,
                                        int row0, int rowmax, int k0,
                                        uint32_t dst, int tid)
{
#pragma unroll
    for (int c = 0; c < 2; c++) {
        int idx = tid + c*256;
        int r = idx >> 2, q = idx & 3;
        int gr = row0 + r;
        int grc = gr < rowmax ? gr : (rowmax - 1);
        const char* src = (const char*)(g + (size_t)grc*ld + k0) + q*16;
        uint32_t d = dst + r*SROW_B + q*16;
        int sz = (gr < rowmax) ? 16 : 0;
        asm volatile("cp.async.cg.shared.global [%0], [%1], 16, %2;"
            :: "r"(d), "l"(src), "r"(sz));
    }
}

// ======================= bf16 mma.sync GEMM (SPLIT: 3-pass hi/lo) ===========
// out = relu(alpha * A[M,K] @ B[Nv,K]^T + bias)
// outmode 0: fp32 C | 1: bf16 hi/lo -> Oh,Ol | 2: bf16 hi -> Oh
// outmode 3: bf16 hi transposed per-head V^T write -> Oh[((b*H+h)*HD+d)*SP_+tok]
template<bool SPLIT>
__global__ __launch_bounds__(256, 1)
void tmm_kernel(const __nv_bfloat16* __restrict__ Ah, const __nv_bfloat16* __restrict__ Al, int lda,
                const __nv_bfloat16* __restrict__ Bh, const __nv_bfloat16* __restrict__ Bl, int ldb,
                const float* __restrict__ bias,
                float* __restrict__ C,
                __nv_bfloat16* __restrict__ Oh, __nv_bfloat16* __restrict__ Ol, int ldc,
                int Mv, int Nv, int K,
                long long sAb, long long sAh, long long sBb, long long sBh,
                long long sCb, long long sCh,
                float alpha, int relu, int outmode)
{
    extern __shared__ char sm[];
    const uint32_t sb = smem_u32(sm);
    const int tid  = threadIdx.x;
    const int wid  = tid >> 5;
    const int lane = tid & 31;
    constexpr int TPS = SPLIT ? 4 : 2;
    const int STG = TPS * MAT_B;

    const long long zb = blockIdx.z / H_;
    const long long zh = blockIdx.z % H_;
    Ah += zb*sAb + zh*sAh;  Bh += zb*sBb + zh*sBh;
    if (SPLIT) { Al += zb*sAb + zh*sAh;  Bl += zb*sBb + zh*sBh; }
    const size_t cOff = (size_t)(zb*sCb + zh*sCh);

    const int m0 = blockIdx.y * 128;
    const int n0 = blockIdx.x * 128;
    const int wm = (wid >> 2) * 64;
    const int wn = (wid & 3) * 32;

    const uint32_t aoff = (uint32_t)(wm + (lane & 15)) * SROW_B + ((lane >> 4) * 16);
    const uint32_t boff = (uint32_t)(wn + (lane & 7) + ((lane >> 4) * 8)) * SROW_B
                        + (((lane >> 3) & 1) * 16);

    float acc[4][4][4];
#pragma unroll
    for (int i = 0; i < 4; i++)
#pragma unroll
        for (int j = 0; j < 4; j++)
#pragma unroll
            for (int e = 0; e < 4; e++) acc[i][j][e] = 0.f;

    const int NC = K >> 5;

    auto issue = [&](int s){
        uint32_t base = sb + (s % NSTG) * STG;
        int k0 = s << 5;
        cp_tile(Ah, lda, m0, Mv, k0, base + 0*MAT_B, tid);
        if (SPLIT) cp_tile(Al, lda, m0, Mv, k0, base + 1*MAT_B, tid);
        cp_tile(Bh, ldb, n0, Nv, k0, base + (SPLIT?2:1)*MAT_B, tid);
        if (SPLIT) cp_tile(Bl, ldb, n0, Nv, k0, base + 3*MAT_B, tid);
    };

#pragma unroll
    for (int s = 0; s < NSTG-1; s++) {          // always NSTG-1 committed groups
        if (s < NC) issue(s);
        CP_COMMIT();
    }

    for (int kc = 0; kc < NC; kc++) {
        CP_WAIT2();
        __syncthreads();
        const uint32_t base = sb + (kc % NSTG) * STG;
        const uint32_t aBH = base + 0*MAT_B + aoff;
        const uint32_t aBL = base + 1*MAT_B + aoff;
        const uint32_t bBH = base + (SPLIT?2:1)*MAT_B + boff;
        const uint32_t bBL = base + 3*MAT_B + boff;

#pragma unroll
        for (int ks = 0; ks < 2; ks++) {
            uint32_t ah[4][4], bh[2][4];
#pragma unroll
            for (int mt = 0; mt < 4; mt++) ldm_x4(ah[mt], aBH + mt*(16*SROW_B) + ks*32);
#pragma unroll
            for (int p = 0; p < 2; p++)    ldm_x4(bh[p], bBH + p*(16*SROW_B) + ks*32);
            if constexpr (SPLIT) {
                uint32_t al[4][4], bl[2][4];
#pragma unroll
                for (int mt = 0; mt < 4; mt++) ldm_x4(al[mt], aBL + mt*(16*SROW_B) + ks*32);
#pragma unroll
                for (int p = 0; p < 2; p++)    ldm_x4(bl[p], bBL + p*(16*SROW_B) + ks*32);
#pragma unroll
                for (int mt = 0; mt < 4; mt++)
#pragma unroll
                    for (int nt = 0; nt < 4; nt++) {
                        uint32_t b0h = bh[nt>>1][(nt&1)*2], b1h = bh[nt>>1][(nt&1)*2+1];
                        uint32_t b0l = bl[nt>>1][(nt&1)*2], b1l = bl[nt>>1][(nt&1)*2+1];
                        MMA16816(acc[mt][nt], ah[mt], b0h, b1h);
                        MMA16816(acc[mt][nt], ah[mt], b0l, b1l);
                        MMA16816(acc[mt][nt], al[mt], b0h, b1h);
                    }
            } else {
#pragma unroll
                for (int mt = 0; mt < 4; mt++)
#pragma unroll
                    for (int nt = 0; nt < 4; nt++) {
                        uint32_t b0h = bh[nt>>1][(nt&1)*2], b1h = bh[nt>>1][(nt&1)*2+1];
                        MMA16816(acc[mt][nt], ah[mt], b0h, b1h);
                    }
            }
        }
        if (kc + NSTG - 1 < NC) issue(kc + NSTG - 1);
        CP_COMMIT();
    }

    // ---- epilogue ----
    const int gq = lane >> 2;
    const int tg = lane & 3;
#pragma unroll
    for (int mt = 0; mt < 4; mt++) {
#pragma unroll
        for (int half = 0; half < 2; half++) {
            int r = m0 + wm + mt*16 + gq + half*8;
            if (r >= Mv) continue;
#pragma unroll
            for (int nt = 0; nt < 4; nt++) {
                int c0 = n0 + wn + nt*8 + tg*2;
                if (c0 >= Nv) continue;
                float v0 = alpha*acc[mt][nt][half*2+0];
                float v1 = alpha*acc[mt][nt][half*2+1];
                if (bias) { v0 += bias[c0]; v1 += bias[c0+1]; }
                if (relu) { v0 = fmaxf(v0, 0.f); v1 = fmaxf(v1, 0.f); }
                if (outmode == 0) {
                    *reinterpret_cast<float2*>(C + cOff + (size_t)r*ldc + c0) = make_float2(v0, v1);
                } else if (outmode == 1) {
                    __nv_bfloat16 h0,l0,h1,l1;
                    split1(v0,h0,l0); split1(v1,h1,l1);
                    size_t base2 = cOff + (size_t)r*ldc + c0;
                    *reinterpret_cast<__nv_bfloat162*>(Oh + base2) = __nv_bfloat162(h0,h1);
                    *reinterpret_cast<__nv_bfloat162*>(Ol + base2) = __nv_bfloat162(l0,l1);
                } else if (outmode == 2) {
                    size_t base2 = cOff + (size_t)r*ldc + c0;
                    *reinterpret_cast<__nv_bfloat162*>(Oh + base2) =
                        __nv_bfloat162(__float2bfloat16(v0), __float2bfloat16(v1));
                } else {
                    // transposed per-head V^T: token r = b*S_+s, dim c
                    int b = r / S_, s = r - b*S_;
                    int h0i = c0 >> 6, d0i = c0 & 63;
                    int h1i = (c0+1) >> 6, d1i = (c0+1) & 63;
                    Oh[(((size_t)b*H_ + h0i)*HD_ + d0i)*SP_ + s] = __float2bfloat16(v0);
                    Oh[(((size_t)b*H_ + h1i)*HD_ + d1i)*SP_ + s] = __float2bfloat16(v1);
                }
            }
        }
    }
}

// ======================= weight transpose + split ============================
__global__ void wsplit_t(const float* __restrict__ W,
                         __nv_bfloat16* __restrict__ oh,
                         __nv_bfloat16* __restrict__ ol, int K, int N)
{
    __shared__ float t[32][33];
    int n = blockIdx.x*32 + threadIdx.x;
    int k0 = blockIdx.y*32;
    #pragma unroll
    for (int j = 0; j < 4; j++)
        t[threadIdx.y + j*8][threadIdx.x] = W[(size_t)(k0 + threadIdx.y + j*8)*N + n];
    __syncthreads();
    int k = k0 + threadIdx.x;
    #pragma unroll
    for (int j = 0; j < 4; j++) {
        int nn = blockIdx.x*32 + threadIdx.y + j*8;
        __nv_bfloat16 h,l; split1(t[threadIdx.x][threadIdx.y + j*8], h, l);
        oh[(size_t)nn*K + k] = h;  ol[(size_t)nn*K + k] = l;
    }
}

// ======================= embed + posenc (+ split) ============================
__global__ void embed_kernel(const int* __restrict__ tokens,
                             const float* __restrict__ emb,
                             float* __restrict__ x,
                             __nv_bfloat16* __restrict__ oh,
                             __nv_bfloat16* __restrict__ ol)
{
    int row = blockIdx.x, d = threadIdx.x;
    int s = row % S_;
    int tok = tokens[row];
    int i = d >> 1;
    float dv  = expf(-(float)(2*i) * (9.210340371976184f / (float)D_));
    float arg = (float)s * dv;
    float pe  = (d & 1) ? cosf(arg) : sinf(arg);
    float val = emb[(size_t)tok*D_ + d] + pe;
    size_t idx = (size_t)row*D_ + d;
    x[idx] = val;
    __nv_bfloat16 h,l; split1(val, h, l); oh[idx]=h; ol[idx]=l;
}

// ======================= scores softmax -> bf16 probs ========================
__global__ void softmax_split(const float* __restrict__ sc,
                              __nv_bfloat16* __restrict__ oh)
{
    __shared__ float row[S_];
    __shared__ float bm[8], bs[8];
    __shared__ float s_m, s_inv;
    int z = blockIdx.x / S_, r = blockIdx.x % S_;
    const float* p = sc + (size_t)z*S_*S_ + (size_t)r*S_;
    const int tid = threadIdx.x, lane = tid & 31, wrp = tid >> 5;

    float m = -3.4e38f;
    for (int i = tid; i < S_; i += 256) { float v = p[i]; row[i] = v; m = fmaxf(m, v); }
    #pragma unroll
    for (int o = 16; o; o >>= 1) m = fmaxf(m, __shfl_xor_sync(0xffffffffu, m, o));
    if (lane == 0) bm[wrp] = m;
    __syncthreads();
    if (tid == 0) {
        float t = bm[0];
        #pragma unroll
        for (int i = 1; i < 8; i++) t = fmaxf(t, bm[i]);
        s_m = t;
    }
    __syncthreads();
    m = s_m;
    float s = 0.f;
    for (int i = tid; i < S_; i += 256) s += __expf(row[i] - m);
    #pragma unroll
    for (int o = 16; o; o >>= 1) s += __shfl_xor_sync(0xffffffffu, s, o);
    if (lane == 0) bs[wrp] = s;
    __syncthreads();
    if (tid == 0) {
        float t = 0.f;
        #pragma unroll
        for (int i = 0; i < 8; i++) t += bs[i];
        s_inv = 1.0f / t;
    }
    __syncthreads();
    const float mm = s_m, inv = s_inv;
    const size_t ob = (size_t)z*S_*SP_ + (size_t)r*SP_;
    for (int c = tid; c < S_; c += 256)
        oh[ob + c] = __float2bfloat16(__expf(row[c] - mm) * inv);
}

// ======================= final V-softmax (smem row, one rd/wr) ===============
__global__ void softmax_big(float* __restrict__ data)
{
    extern __shared__ float row[];
    float* p = data + (size_t)blockIdx.x * V_;
    const int tid = threadIdx.x, lane = tid & 31, wrp = tid >> 5;
    __shared__ float bm[8], bs[8];
    __shared__ float s_m, s_inv;

    float m = -3.4e38f;
    for (int i = tid; i < V_; i += 256) { float v = p[i]; row[i] = v; m = fmaxf(m, v); }
    #pragma unroll
    for (int o = 16; o; o >>= 1) m = fmaxf(m, __shfl_xor_sync(0xffffffffu, m, o));
    if (lane == 0) bm[wrp] = m;
    __syncthreads();
    if (tid == 0) {
        float t = bm[0];
        #pragma unroll
        for (int i = 1; i < 8; i++) t = fmaxf(t, bm[i]);
        s_m = t;
    }
    __syncthreads();
    m = s_m;
    float s = 0.f;
    for (int i = tid; i < V_; i += 256) s += __expf(row[i] - m);
    #pragma unroll
    for (int o = 16; o; o >>= 1) s += __shfl_xor_sync(0xffffffffu, s, o);
    if (lane == 0) bs[wrp] = s;
    __syncthreads();
    if (tid == 0) {
        float t = 0.f;
        #pragma unroll
        for (int i = 0; i < 8; i++) t += bs[i];
        s_inv = 1.0f / t;
    }
    __syncthreads();
    const float mm = s_m, inv = s_inv;
    for (int i = tid; i < V_; i += 256)
        p[i] = __expf(row[i] - mm) * inv;
}

// ======================= residual add + LayerNorm (+ split) ==================
__global__ void add_ln_kernel(const float* __restrict__ xin,
                              const float* __restrict__ res,
                              const float* __restrict__ g,
                              const float* __restrict__ b,
                              float* __restrict__ xout,
                              __nv_bfloat16* __restrict__ oh,
                              __nv_bfloat16* __restrict__ ol)
{
    const int row = blockIdx.x, d = threadIdx.x;
    const int lane = d & 31, wrp = d >> 5;
    size_t idx = (size_t)row*D_ + d;
    float y = xin[idx] + res[idx];
    __shared__ float bsum[16], bsq[16];
    __shared__ float s_mu, s_rs;
    float s1 = y, s2 = y*y;
    #pragma unroll
    for (int o = 16; o; o >>= 1) {
        s1 += __shfl_xor_sync(0xffffffffu, s1, o);
        s2 += __shfl_xor_sync(0xffffffffu, s2, o);
    }
    if (lane == 0) { bsum[wrp] = s1; bsq[wrp] = s2; }
    __syncthreads();
    if (d == 0) {
        float a = 0.f, c = 0.f;
        #pragma unroll
        for (int i = 0; i < 16; i++) { a += bsum[i]; c += bsq[i]; }
        float mu = a * (1.0f/D_);
        float var = c * (1.0f/D_) - mu*mu;
        s_mu = mu; s_rs = rsqrtf(var + 1e-5f);
    }
    __syncthreads();
    float val = (y - s_mu) * s_rs * g[d] + b[d];
    xout[idx] = val;
    __nv_bfloat16 h,l; split1(val, h, l); oh[idx]=h; ol[idx]=l;
}

// ======================= launcher ============================================
#define SMEM_SPLIT  (NSTG*4*MAT_B)   // 163840
#define SMEM_SINGLE (NSTG*2*MAT_B)   // 81920

extern "C" void kernel_launch(void* const* d_in, const int* in_sizes, int n_in,
                              void* d_out, int out_size)
{
    (void)in_sizes; (void)n_in; (void)out_size;
    const int*   tokens = (const int*)  d_in[0];
    const float* emb  = (const float*)d_in[1];
    const float* wq   = (const float*)d_in[2];
    const float* bq   = (const float*)d_in[3];
    const float* wk   = (const float*)d_in[4];
    const float* bk   = (const float*)d_in[5];
    const float* wv   = (const float*)d_in[6];
    const float* bv   = (const float*)d_in[7];
    const float* wo   = (const float*)d_in[8];
    const float* bo   = (const float*)d_in[9];
    const float* ln1g = (const float*)d_in[10];
    const float* ln1b = (const float*)d_in[11];
    const float* w1   = (const float*)d_in[12];
    const float* b1   = (const float*)d_in[13];
    const float* w2   = (const float*)d_in[14];
    const float* b2   = (const float*)d_in[15];
    const float* ln2g = (const float*)d_in[16];
    const float* ln2b = (const float*)d_in[17];
    const float* fcw  = (const float*)d_in[18];
    const float* fcb  = (const float*)d_in[19];
    float* out = (float*)d_out;

    float *x,*t,*sc;
    __nv_bfloat16 *ah,*al,*hh,*hl,*qh,*kh,*bh,*bl,*sh,*vh;
    cudaGetSymbolAddress((void**)&x,  g_x);  cudaGetSymbolAddress((void**)&t,  g_t);
    cudaGetSymbolAddress((void**)&sc, g_s);
    cudaGetSymbolAddress((void**)&ah, g_ah); cudaGetSymbolAddress((void**)&al, g_al);
    cudaGetSymbolAddress((void**)&hh, g_hh); cudaGetSymbolAddress((void**)&hl, g_hl);
    cudaGetSymbolAddress((void**)&qh, g_qh); cudaGetSymbolAddress((void**)&kh, g_kh);
    cudaGetSymbolAddress((void**)&bh, g_bh); cudaGetSymbolAddress((void**)&bl, g_bl);
    cudaGetSymbolAddress((void**)&sh, g_sh); cudaGetSymbolAddress((void**)&vh, g_vh);

    cudaFuncSetAttribute(tmm_kernel<true>,  cudaFuncAttributeMaxDynamicSharedMemorySize, SMEM_SPLIT);
    cudaFuncSetAttribute(tmm_kernel<false>, cudaFuncAttributeMaxDynamicSharedMemorySize, SMEM_SINGLE);
    cudaFuncSetAttribute(softmax_big, cudaFuncAttributeMaxDynamicSharedMemorySize, V_*4);

    embed_kernel<<<M_, D_>>>(tokens, emb, x, ah, al);

    const dim3 gDD (D_/128,  (M_+127)/128);
    const dim3 gFF (FF_/128, (M_+127)/128);
    const dim3 gSC ((S_+127)/128, (S_+127)/128, B_*H_);
    const dim3 gCX (1, (S_+127)/128, B_*H_);
    const dim3 tb (32, 8);

    for (int l = 0; l < L_; l++) {
        const float* lwq = wq + (size_t)l*D_*D_;
        const float* lwk = wk + (size_t)l*D_*D_;
        const float* lwv = wv + (size_t)l*D_*D_;
        const float* lwo = wo + (size_t)l*D_*D_;
        const float* lw1 = w1 + (size_t)l*D_*FF_;
        const float* lw2 = w2 + (size_t)l*FF_*D_;

        // ---- QKV projections (single bf16) ----
        wsplit_t<<<dim3(D_/32, D_/32), tb>>>(lwq, bh, bl, D_, D_);
        tmm_kernel<false><<<gDD, 256, SMEM_SINGLE>>>(ah, nullptr, D_, bh, nullptr, D_,
            bq + l*D_, nullptr, qh, nullptr, D_, M_, D_, D_, 0,0,0,0,0,0, 1.f, 0, 2);
        wsplit_t<<<dim3(D_/32, D_/32), tb>>>(lwk, bh, bl, D_, D_);
        tmm_kernel<false><<<gDD, 256, SMEM_SINGLE>>>(ah, nullptr, D_, bh, nullptr, D_,
            bk + l*D_, nullptr, kh, nullptr, D_, M_, D_, D_, 0,0,0,0,0,0, 1.f, 0, 2);
        wsplit_t<<<dim3(D_/32, D_/32), tb>>>(lwv, bh, bl, D_, D_);
        tmm_kernel<false><<<gDD, 256, SMEM_SINGLE>>>(ah, nullptr, D_, bh, nullptr, D_,
            bv + l*D_, nullptr, vh, nullptr, D_, M_, D_, D_, 0,0,0,0,0,0, 1.f, 0, 3);

        // ---- scores = QK^T/8 (single, K=64) ----
        tmm_kernel<false><<<gSC, 256, SMEM_SINGLE>>>(qh, nullptr, D_, kh, nullptr, D_,
            nullptr, sc, nullptr, nullptr, S_, S_, S_, 64,
            (long long)S_*D_, HD_, (long long)S_*D_, HD_,
            (long long)H_*S_*S_, (long long)S_*S_, 0.125f, 0, 0);

        softmax_split<<<B_*H_*S_, 256>>>(sc, sh);

        // ---- ctx = probs @ V^T (single, K=1024 padded) -> bf16 into qh ----
        tmm_kernel<false><<<gCX, 256, SMEM_SINGLE>>>(sh, nullptr, SP_, vh, nullptr, SP_,
            nullptr, nullptr, qh, nullptr, D_, S_, HD_, SP_,
            (long long)H_*S_*SP_, (long long)S_*SP_,
            (long long)H_*HD_*SP_, (long long)HD_*SP_,
            (long long)S_*D_, HD_, 1.f, 0, 2);

        // ---- output projection (single) ----
        wsplit_t<<<dim3(D_/32, D_/32), tb>>>(lwo, bh, bl, D_, D_);
        tmm_kernel<false><<<gDD, 256, SMEM_SINGLE>>>(qh, nullptr, D_, bh, nullptr, D_,
            bo + l*D_, t, nullptr, nullptr, D_, M_, D_, D_, 0,0,0,0,0,0, 1.f, 0, 0);

        add_ln_kernel<<<M_, D_>>>(x, t, ln1g + l*D_, ln1b + l*D_, x, ah, al);

        // ---- FFN (split 3-pass) ----
        wsplit_t<<<dim3(FF_/32, D_/32), tb>>>(lw1, bh, bl, D_, FF_);
        tmm_kernel<true><<<gFF, 256, SMEM_SPLIT>>>(ah, al, D_, bh, bl, D_,
            b1 + l*FF_, nullptr, hh, hl, FF_, M_, FF_, D_, 0,0,0,0,0,0, 1.f, 1, 1);
        wsplit_t<<<dim3(D_/32, FF_/32), tb>>>(lw2, bh, bl, FF_, D_);
        tmm_kernel<true><<<gDD, 256, SMEM_SPLIT>>>(hh, hl, FF_, bh, bl, FF_,
            b2 + l*D_, t, nullptr, nullptr, D_, M_, D_, FF_, 0,0,0,0,0,0, 1.f, 0, 0);

        add_ln_kernel<<<M_, D_>>>(x, t, ln2g + l*D_, ln2b + l*D_, x, ah, al);
    }

    // ---- logits (split) + softmax ----
    wsplit_t<<<dim3(V_/32, D_/32), tb>>>(fcw, bh, bl, D_, V_);
    tmm_kernel<true><<<dim3(V_/128, (M_+127)/128), 256, SMEM_SPLIT>>>(ah, al, D_, bh, bl, D_,
        fcb, out, nullptr, nullptr, V_, M_, V_, D_, 0,0,0,0,0,0, 1.f, 0, 0);
    softmax_big<<<M_, 256, V_*4>>>(out);
}

// round 6
// speedup vs baseline: 2.5442x; 1.1256x over previous
#include <cuda_runtime.h>
#include <cuda_fp16.h>
#include <math.h>
#include <stdint.h>

#define B_  4
#define S_  1000
#define D_  512
#define H_  8
#define L_  4
#define V_  32000
#define HD_ 64
#define FF_ 2048
#define M_  (B_*S_)
#define SP_ 1024

// ======================= scratch (device globals, zero-init) =================
__device__ __align__(128) float g_x[M_*D_];
__device__ __align__(128) float g_t[M_*D_];
__device__ __align__(128) float g_s[B_*H_*S_*S_];                 // scores fp32
__device__ __align__(128) float g_qkvb[3*D_];                      // merged bias
__device__ __align__(128) __half g_ah[M_*D_],  g_al[M_*D_];        // x hi/lo
__device__ __align__(128) __half g_hh[M_*FF_], g_hl[M_*FF_];       // h hi/lo
__device__ __align__(128) __half g_qh[M_*D_];
__device__ __align__(128) __half g_kh[M_*D_];
__device__ __align__(128) __half g_bh[(size_t)V_*D_];              // W^T fp16
__device__ __align__(128) __half g_sh[(size_t)B_*H_*S_*SP_];       // probs (pad=0)
__device__ __align__(128) __half g_vh[(size_t)B_*H_*HD_*SP_];      // V^T (pad=0)

// ======================= helpers =============================================
__device__ __forceinline__ uint32_t smem_u32(const void* p){
    uint32_t a;
    asm("{ .reg .u64 t; cvta.to.shared.u64 t, %1; cvt.u32.u64 %0, t; }" : "=r"(a) : "l"(p));
    return a;
}
__device__ __forceinline__ void split1(float v, __half& h, __half& l){
    h = __float2half(v);
    l = __float2half(v - __half2float(h));
}
__device__ __forceinline__ void ldm_x4(uint32_t* r, uint32_t addr){
    asm volatile("ldmatrix.sync.aligned.m8n8.x4.shared.b16 {%0,%1,%2,%3}, [%4];"
        : "=r"(r[0]), "=r"(r[1]), "=r"(r[2]), "=r"(r[3]) : "r"(addr));
}
#define MMAF16(c, a, b0v, b1v) \
    asm volatile("mma.sync.aligned.m16n8k16.row.col.f32.f16.f16.f32 " \
        "{%0,%1,%2,%3}, {%4,%5,%6,%7}, {%8,%9}, {%0,%1,%2,%3};" \
        : "+f"((c)[0]), "+f"((c)[1]), "+f"((c)[2]), "+f"((c)[3]) \
        : "r"((a)[0]), "r"((a)[1]), "r"((a)[2]), "r"((a)[3]), "r"(b0v), "r"(b1v))
#define CP_COMMIT() asm volatile("cp.async.commit_group;" ::: "memory")
#define CP_WAIT2()  asm volatile("cp.async.wait_group 2;" ::: "memory")

// ======================= smem tile layout ====================================
#define SROW_B   80
#define MAT_B    (128*SROW_B)
#define NSTG     4

__device__ __forceinline__ void cp_tile(const __half* __restrict__ g, int ld,
                                        int row0, int rowmax, int k0,
                                        uint32_t dst, int tid)
{
#pragma unroll
    for (int c = 0; c < 2; c++) {
        int idx = tid + c*256;
        int r = idx >> 2, q = idx & 3;
        int gr = row0 + r;
        int grc = gr < rowmax ? gr : (rowmax - 1);
        const char* src = (const char*)(g + (size_t)grc*ld + k0) + q*16;
        uint32_t d = dst + r*SROW_B + q*16;
        int sz = (gr < rowmax) ? 16 : 0;
        asm volatile("cp.async.cg.shared.global [%0], [%1], 16, %2;"
            :: "r"(d), "l"(src), "r"(sz));
    }
}

// ======================= fp16 mma.sync GEMM ==================================
// SPLIT=false: C = act(alpha * Ah @ Bh^T + bias)        (1 MMA pass)
// SPLIT=true : C = act(alpha * (Ah+Al) @ Bh^T + bias)   (2 MMA passes)
// outmode 0: fp32 C | 1: fp16 hi/lo -> Oh,Ol | 2: fp16 hi -> Oh
// outmode 4: merged QKV: c0<512 -> Oh(q), c0<1024 -> Ol(k), else per-head V^T -> (half*)C
template<bool SPLIT>
__global__ __launch_bounds__(256, 1)
void tmm_kernel(const __half* __restrict__ Ah, const __half* __restrict__ Al, int lda,
                const __half* __restrict__ Bh, int ldb,
                const float* __restrict__ bias,
                float* __restrict__ C,
                __half* __restrict__ Oh, __half* __restrict__ Ol, int ldc,
                int Mv, int Nv, int K,
                long long sAb, long long sAh, long long sBb, long long sBh,
                long long sCb, long long sCh,
                float alpha, int relu, int outmode)
{
    extern __shared__ char sm[];
    const uint32_t sb = smem_u32(sm);
    const int tid  = threadIdx.x;
    const int wid  = tid >> 5;
    const int lane = tid & 31;
    constexpr int TPS = SPLIT ? 3 : 2;
    const int STG = TPS * MAT_B;

    const long long zb = blockIdx.z / H_;
    const long long zh = blockIdx.z % H_;
    Ah += zb*sAb + zh*sAh;  Bh += zb*sBb + zh*sBh;
    if (SPLIT) Al += zb*sAb + zh*sAh;
    const size_t cOff = (size_t)(zb*sCb + zh*sCh);

    const int m0 = blockIdx.y * 128;
    const int n0 = blockIdx.x * 128;
    const int wm = (wid >> 2) * 64;
    const int wn = (wid & 3) * 32;

    const uint32_t aoff = (uint32_t)(wm + (lane & 15)) * SROW_B + ((lane >> 4) * 16);
    const uint32_t boff = (uint32_t)(wn + (lane & 7) + ((lane >> 4) * 8)) * SROW_B
                        + (((lane >> 3) & 1) * 16);

    float acc[4][4][4];
#pragma unroll
    for (int i = 0; i < 4; i++)
#pragma unroll
        for (int j = 0; j < 4; j++)
#pragma unroll
            for (int e = 0; e < 4; e++) acc[i][j][e] = 0.f;

    const int NC = K >> 5;

    auto issue = [&](int s){
        uint32_t base = sb + (s % NSTG) * STG;
        int k0 = s << 5;
        cp_tile(Ah, lda, m0, Mv, k0, base + 0*MAT_B, tid);
        if (SPLIT) cp_tile(Al, lda, m0, Mv, k0, base + 1*MAT_B, tid);
        cp_tile(Bh, ldb, n0, Nv, k0, base + (SPLIT?2:1)*MAT_B, tid);
    };

#pragma unroll
    for (int s = 0; s < NSTG-1; s++) {
        if (s < NC) issue(s);
        CP_COMMIT();
    }

    for (int kc = 0; kc < NC; kc++) {
        CP_WAIT2();
        __syncthreads();
        const uint32_t base = sb + (kc % NSTG) * STG;
        const uint32_t aBH = base + 0*MAT_B + aoff;
        const uint32_t aBL = base + 1*MAT_B + aoff;
        const uint32_t bBH = base + (SPLIT?2:1)*MAT_B + boff;

#pragma unroll
        for (int ks = 0; ks < 2; ks++) {
            uint32_t ah[4][4], bh[2][4];
#pragma unroll
            for (int mt = 0; mt < 4; mt++) ldm_x4(ah[mt], aBH + mt*(16*SROW_B) + ks*32);
#pragma unroll
            for (int p = 0; p < 2; p++)    ldm_x4(bh[p], bBH + p*(16*SROW_B) + ks*32);
            if constexpr (SPLIT) {
                uint32_t al[4][4];
#pragma unroll
                for (int mt = 0; mt < 4; mt++) ldm_x4(al[mt], aBL + mt*(16*SROW_B) + ks*32);
#pragma unroll
                for (int mt = 0; mt < 4; mt++)
#pragma unroll
                    for (int nt = 0; nt < 4; nt++) {
                        uint32_t b0 = bh[nt>>1][(nt&1)*2], b1 = bh[nt>>1][(nt&1)*2+1];
                        MMAF16(acc[mt][nt], ah[mt], b0, b1);
                        MMAF16(acc[mt][nt], al[mt], b0, b1);
                    }
            } else {
#pragma unroll
                for (int mt = 0; mt < 4; mt++)
#pragma unroll
                    for (int nt = 0; nt < 4; nt++) {
                        uint32_t b0 = bh[nt>>1][(nt&1)*2], b1 = bh[nt>>1][(nt&1)*2+1];
                        MMAF16(acc[mt][nt], ah[mt], b0, b1);
                    }
            }
        }
        if (kc + NSTG - 1 < NC) issue(kc + NSTG - 1);
        CP_COMMIT();
    }

    // ---- epilogue ----
    const int gq = lane >> 2;
    const int tg = lane & 3;
#pragma unroll
    for (int mt = 0; mt < 4; mt++) {
#pragma unroll
        for (int half_ = 0; half_ < 2; half_++) {
            int r = m0 + wm + mt*16 + gq + half_*8;
            if (r >= Mv) continue;
#pragma unroll
            for (int nt = 0; nt < 4; nt++) {
                int c0 = n0 + wn + nt*8 + tg*2;
                if (c0 >= Nv) continue;
                float v0 = alpha*acc[mt][nt][half_*2+0];
                float v1 = alpha*acc[mt][nt][half_*2+1];
                if (bias) { v0 += bias[c0]; v1 += bias[c0+1]; }
                if (relu) { v0 = fmaxf(v0, 0.f); v1 = fmaxf(v1, 0.f); }
                if (outmode == 0) {
                    *reinterpret_cast<float2*>(C + cOff + (size_t)r*ldc + c0) = make_float2(v0, v1);
                } else if (outmode == 1) {
                    __half h0,l0,h1,l1;
                    split1(v0,h0,l0); split1(v1,h1,l1);
                    size_t base2 = cOff + (size_t)r*ldc + c0;
                    *reinterpret_cast<__half2*>(Oh + base2) = __half2(h0,h1);
                    *reinterpret_cast<__half2*>(Ol + base2) = __half2(l0,l1);
                } else if (outmode == 2) {
                    size_t base2 = cOff + (size_t)r*ldc + c0;
                    *reinterpret_cast<__half2*>(Oh + base2) =
                        __half2(__float2half(v0), __float2half(v1));
                } else {
                    // merged QKV epilogue
                    if (c0 < 1024) {
                        __half2 hv(__float2half(v0), __float2half(v1));
                        if (c0 < 512)
                            *reinterpret_cast<__half2*>(Oh + (size_t)r*D_ + c0) = hv;
                        else
                            *reinterpret_cast<__half2*>(Ol + (size_t)r*D_ + (c0-512)) = hv;
                    } else {
                        __half* Vt = reinterpret_cast<__half*>(C);
                        int b = r / S_, s = r - b*S_;
                        int cc = c0 - 1024;
                        int hi = cc >> 6, di = cc & 63;
                        Vt[(((size_t)b*H_ + hi)*HD_ + di    )*SP_ + s] = __float2half(v0);
                        Vt[(((size_t)b*H_ + hi)*HD_ + di + 1)*SP_ + s] = __float2half(v1);
                    }
                }
            }
        }
    }
}

// ======================= weight transpose -> fp16 ============================
// W[K,N] row-major -> out[N,K] fp16
__global__ void wsplit_t(const float* __restrict__ W,
                         __half* __restrict__ oh, int K, int N)
{
    __shared__ float t[32][33];
    int n = blockIdx.x*32 + threadIdx.x;
    int k0 = blockIdx.y*32;
    #pragma unroll
    for (int j = 0; j < 4; j++)
        t[threadIdx.y + j*8][threadIdx.x] = W[(size_t)(k0 + threadIdx.y + j*8)*N + n];
    __syncthreads();
    int k = k0 + threadIdx.x;
    #pragma unroll
    for (int j = 0; j < 4; j++) {
        int nn = blockIdx.x*32 + threadIdx.y + j*8;
        oh[(size_t)nn*K + k] = __float2half(t[threadIdx.x][threadIdx.y + j*8]);
    }
}

// ======================= embed + posenc (+ hi/lo split) ======================
__global__ void embed_kernel(const int* __restrict__ tokens,
                             const float* __restrict__ emb,
                             float* __restrict__ x,
                             __half* __restrict__ oh,
                             __half* __restrict__ ol)
{
    int row = blockIdx.x, d = threadIdx.x;
    int s = row % S_;
    int tok = tokens[row];
    int i = d >> 1;
    float dv  = expf(-(float)(2*i) * (9.210340371976184f / (float)D_));
    float arg = (float)s * dv;
    float pe  = (d & 1) ? cosf(arg) : sinf(arg);
    float val = emb[(size_t)tok*D_ + d] + pe;
    size_t idx = (size_t)row*D_ + d;
    x[idx] = val;
    __half h,l; split1(val, h, l); oh[idx]=h; ol[idx]=l;
}

// ======================= scores softmax -> fp16 probs ========================
__global__ void softmax_split(const float* __restrict__ sc,
                              __half* __restrict__ oh)
{
    __shared__ float row[S_];
    __shared__ float bm[8], bs[8];
    __shared__ float s_m, s_inv;
    int z = blockIdx.x / S_, r = blockIdx.x % S_;
    const float* p = sc + (size_t)z*S_*S_ + (size_t)r*S_;
    const int tid = threadIdx.x, lane = tid & 31, wrp = tid >> 5;

    float m = -3.4e38f;
    for (int i = tid; i < S_; i += 256) { float v = p[i]; row[i] = v; m = fmaxf(m, v); }
    #pragma unroll
    for (int o = 16; o; o >>= 1) m = fmaxf(m, __shfl_xor_sync(0xffffffffu, m, o));
    if (lane == 0) bm[wrp] = m;
    __syncthreads();
    if (tid == 0) {
        float t = bm[0];
        #pragma unroll
        for (int i = 1; i < 8; i++) t = fmaxf(t, bm[i]);
        s_m = t;
    }
    __syncthreads();
    m = s_m;
    float s = 0.f;
    for (int i = tid; i < S_; i += 256) s += __expf(row[i] - m);
    #pragma unroll
    for (int o = 16; o; o >>= 1) s += __shfl_xor_sync(0xffffffffu, s, o);
    if (lane == 0) bs[wrp] = s;
    __syncthreads();
    if (tid == 0) {
        float t = 0.f;
        #pragma unroll
        for (int i = 0; i < 8; i++) t += bs[i];
        s_inv = 1.0f / t;
    }
    __syncthreads();
    const float mm = s_m, inv = s_inv;
    const size_t ob = (size_t)z*S_*SP_ + (size_t)r*SP_;
    for (int c = tid; c < S_; c += 256)
        oh[ob + c] = __float2half(__expf(row[c] - mm) * inv);
}

// ======================= final V-softmax (smem row) ==========================
__global__ void softmax_big(float* __restrict__ data)
{
    extern __shared__ float row[];
    float* p = data + (size_t)blockIdx.x * V_;
    const int tid = threadIdx.x, lane = tid & 31, wrp = tid >> 5;
    __shared__ float bm[8], bs[8];
    __shared__ float s_m, s_inv;

    float m = -3.4e38f;
    for (int i = tid; i < V_; i += 256) { float v = p[i]; row[i] = v; m = fmaxf(m, v); }
    #pragma unroll
    for (int o = 16; o; o >>= 1) m = fmaxf(m, __shfl_xor_sync(0xffffffffu, m, o));
    if (lane == 0) bm[wrp] = m;
    __syncthreads();
    if (tid == 0) {
        float t = bm[0];
        #pragma unroll
        for (int i = 1; i < 8; i++) t = fmaxf(t, bm[i]);
        s_m = t;
    }
    __syncthreads();
    m = s_m;
    float s = 0.f;
    for (int i = tid; i < V_; i += 256) s += __expf(row[i] - m);
    #pragma unroll
    for (int o = 16; o; o >>= 1) s += __shfl_xor_sync(0xffffffffu, s, o);
    if (lane == 0) bs[wrp] = s;
    __syncthreads();
    if (tid == 0) {
        float t = 0.f;
        #pragma unroll
        for (int i = 0; i < 8; i++) t += bs[i];
        s_inv = 1.0f / t;
    }
    __syncthreads();
    const float mm = s_m, inv = s_inv;
    for (int i = tid; i < V_; i += 256)
        p[i] = __expf(row[i] - mm) * inv;
}

// ======================= residual add + LayerNorm (+ split) ==================
__global__ void add_ln_kernel(const float* __restrict__ xin,
                              const float* __restrict__ res,
                              const float* __restrict__ g,
                              const float* __restrict__ b,
                              float* __restrict__ xout,
                              __half* __restrict__ oh,
                              __half* __restrict__ ol)
{
    const int row = blockIdx.x, d = threadIdx.x;
    const int lane = d & 31, wrp = d >> 5;
    size_t idx = (size_t)row*D_ + d;
    float y = xin[idx] + res[idx];
    __shared__ float bsum[16], bsq[16];
    __shared__ float s_mu, s_rs;
    float s1 = y, s2 = y*y;
    #pragma unroll
    for (int o = 16; o; o >>= 1) {
        s1 += __shfl_xor_sync(0xffffffffu, s1, o);
        s2 += __shfl_xor_sync(0xffffffffu, s2, o);
    }
    if (lane == 0) { bsum[wrp] = s1; bsq[wrp] = s2; }
    __syncthreads();
    if (d == 0) {
        float a = 0.f, c = 0.f;
        #pragma unroll
        for (int i = 0; i < 16; i++) { a += bsum[i]; c += bsq[i]; }
        float mu = a * (1.0f/D_);
        float var = c * (1.0f/D_) - mu*mu;
        s_mu = mu; s_rs = rsqrtf(var + 1e-5f);
    }
    __syncthreads();
    float val = (y - s_mu) * s_rs * g[d] + b[d];
    xout[idx] = val;
    __half h,l; split1(val, h, l); oh[idx]=h; ol[idx]=l;
}

// ======================= launcher ============================================
#define SMEM_SPLIT  (NSTG*3*MAT_B)   // 122880
#define SMEM_SINGLE (NSTG*2*MAT_B)   // 81920

extern "C" void kernel_launch(void* const* d_in, const int* in_sizes, int n_in,
                              void* d_out, int out_size)
{
    (void)in_sizes; (void)n_in; (void)out_size;
    const int*   tokens = (const int*)  d_in[0];
    const float* emb  = (const float*)d_in[1];
    const float* wq   = (const float*)d_in[2];
    const float* bq   = (const float*)d_in[3];
    const float* wk   = (const float*)d_in[4];
    const float* bk   = (const float*)d_in[5];
    const float* wv   = (const float*)d_in[6];
    const float* bv   = (const float*)d_in[7];
    const float* wo   = (const float*)d_in[8];
    const float* bo   = (const float*)d_in[9];
    const float* ln1g = (const float*)d_in[10];
    const float* ln1b = (const float*)d_in[11];
    const float* w1   = (const float*)d_in[12];
    const float* b1   = (const float*)d_in[13];
    const float* w2   = (const float*)d_in[14];
    const float* b2   = (const float*)d_in[15];
    const float* ln2g = (const float*)d_in[16];
    const float* ln2b = (const float*)d_in[17];
    const float* fcw  = (const float*)d_in[18];
    const float* fcb  = (const float*)d_in[19];
    float* out = (float*)d_out;

    float *x,*t,*sc,*qkvb;
    __half *ah,*al,*hh,*hl,*qh,*kh,*bh,*sh,*vh;
    cudaGetSymbolAddress((void**)&x,  g_x);  cudaGetSymbolAddress((void**)&t,  g_t);
    cudaGetSymbolAddress((void**)&sc, g_s);  cudaGetSymbolAddress((void**)&qkvb, g_qkvb);
    cudaGetSymbolAddress((void**)&ah, g_ah); cudaGetSymbolAddress((void**)&al, g_al);
    cudaGetSymbolAddress((void**)&hh, g_hh); cudaGetSymbolAddress((void**)&hl, g_hl);
    cudaGetSymbolAddress((void**)&qh, g_qh); cudaGetSymbolAddress((void**)&kh, g_kh);
    cudaGetSymbolAddress((void**)&bh, g_bh);
    cudaGetSymbolAddress((void**)&sh, g_sh); cudaGetSymbolAddress((void**)&vh, g_vh);

    cudaFuncSetAttribute(tmm_kernel<true>,  cudaFuncAttributeMaxDynamicSharedMemorySize, SMEM_SPLIT);
    cudaFuncSetAttribute(tmm_kernel<false>, cudaFuncAttributeMaxDynamicSharedMemorySize, SMEM_SINGLE);
    cudaFuncSetAttribute(softmax_big, cudaFuncAttributeMaxDynamicSharedMemorySize, V_*4);

    embed_kernel<<<M_, D_>>>(tokens, emb, x, ah, al);

    const dim3 gQKV(1536/128, (M_+127)/128);
    const dim3 gDD (D_/128,  (M_+127)/128);
    const dim3 gFF (FF_/128, (M_+127)/128);
    const dim3 gSC ((S_+127)/128, (S_+127)/128, B_*H_);
    const dim3 gCX (1, (S_+127)/128, B_*H_);
    const dim3 tb (32, 8);

    for (int l = 0; l < L_; l++) {
        const float* lwq = wq + (size_t)l*D_*D_;
        const float* lwk = wk + (size_t)l*D_*D_;
        const float* lwv = wv + (size_t)l*D_*D_;
        const float* lwo = wo + (size_t)l*D_*D_;
        const float* lw1 = w1 + (size_t)l*D_*FF_;
        const float* lw2 = w2 + (size_t)l*FF_*D_;

        // ---- merged QKV projection (single fp16) ----
        wsplit_t<<<dim3(D_/32, D_/32), tb>>>(lwq, bh,             D_, D_);
        wsplit_t<<<dim3(D_/32, D_/32), tb>>>(lwk, bh +  512*D_,   D_, D_);
        wsplit_t<<<dim3(D_/32, D_/32), tb>>>(lwv, bh + 1024*D_,   D_, D_);
        cudaMemcpyAsync(qkvb,        bq + l*D_, D_*4, cudaMemcpyDeviceToDevice);
        cudaMemcpyAsync(qkvb + D_,   bk + l*D_, D_*4, cudaMemcpyDeviceToDevice);
        cudaMemcpyAsync(qkvb + 2*D_, bv + l*D_, D_*4, cudaMemcpyDeviceToDevice);
        tmm_kernel<false><<<gQKV, 256, SMEM_SINGLE>>>(ah, nullptr, D_, bh, D_,
            qkvb, (float*)vh, qh, kh, D_, M_, 1536, D_, 0,0,0,0,0,0, 1.f, 0, 4);

        // ---- scores = QK^T/8 (single, K=64) ----
        tmm_kernel<false><<<gSC, 256, SMEM_SINGLE>>>(qh, nullptr, D_, kh, D_,
            nullptr, sc, nullptr, nullptr, S_, S_, S_, 64,
            (long long)S_*D_, HD_, (long long)S_*D_, HD_,
            (long long)H_*S_*S_, (long long)S_*S_, 0.125f, 0, 0);

        softmax_split<<<B_*H_*S_, 256>>>(sc, sh);

        // ---- ctx = probs @ V^T (single, K=1024 padded) -> fp16 into qh ----
        tmm_kernel<false><<<gCX, 256, SMEM_SINGLE>>>(sh, nullptr, SP_, vh, SP_,
            nullptr, nullptr, qh, nullptr, D_, S_, HD_, SP_,
            (long long)H_*S_*SP_, (long long)S_*SP_,
            (long long)H_*HD_*SP_, (long long)HD_*SP_,
            (long long)S_*D_, HD_, 1.f, 0, 2);

        // ---- output projection (single) ----
        wsplit_t<<<dim3(D_/32, D_/32), tb>>>(lwo, bh, D_, D_);
        tmm_kernel<false><<<gDD, 256, SMEM_SINGLE>>>(qh, nullptr, D_, bh, D_,
            bo + l*D_, t, nullptr, nullptr, D_, M_, D_, D_, 0,0,0,0,0,0, 1.f, 0, 0);

        add_ln_kernel<<<M_, D_>>>(x, t, ln1g + l*D_, ln1b + l*D_, x, ah, al);

        // ---- FFN (2-pass split) ----
        wsplit_t<<<dim3(FF_/32, D_/32), tb>>>(lw1, bh, D_, FF_);
        tmm_kernel<true><<<gFF, 256, SMEM_SPLIT>>>(ah, al, D_, bh, D_,
            b1 + l*FF_, nullptr, hh, hl, FF_, M_, FF_, D_, 0,0,0,0,0,0, 1.f, 1, 1);
        wsplit_t<<<dim3(D_/32, FF_/32), tb>>>(lw2, bh, FF_, D_);
        tmm_kernel<true><<<gDD, 256, SMEM_SPLIT>>>(hh, hl, FF_, bh, FF_,
            b2 + l*D_, t, nullptr, nullptr, D_, M_, D_, FF_, 0,0,0,0,0,0, 1.f, 0, 0);

        add_ln_kernel<<<M_, D_>>>(x, t, ln2g + l*D_, ln2b + l*D_, x, ah, al);
    }

    // ---- logits (2-pass split) + softmax ----
    wsplit_t<<<dim3(V_/32, D_/32), tb>>>(fcw, bh, D_, V_);
    tmm_kernel<true><<<dim3(V_/128, (M_+127)/128), 256, SMEM_SPLIT>>>(ah, al, D_, bh, D_,
        fcb, out, nullptr, nullptr, V_, M_, V_, D_, 0,0,0,0,0,0, 1.f, 0, 0);
    softmax_big<<<M_, 256, V_*4>>>(out);
}

// round 8
// speedup vs baseline: 2.7764x; 1.0913x over previous
#include <cuda_runtime.h>
#include <cuda_fp16.h>
#include <math.h>
#include <stdint.h>

#define B_  4
#define S_  1000
#define D_  512
#define H_  8
#define L_  4
#define V_  32000
#define HD_ 64
#define FF_ 2048
#define M_  (B_*S_)
#define SP_ 1024

// ======================= scratch (device globals, zero-init) =================
__device__ __align__(128) float g_x[M_*D_];
__device__ __align__(128) float g_t[M_*D_];
__device__ __align__(128) __half g_sc[(size_t)B_*H_*S_*S_];        // scores fp16
__device__ __align__(128) float g_qkvb[3*D_];
__device__ __align__(128) __half g_ah[M_*D_],  g_al[M_*D_];
__device__ __align__(128) __half g_hh[M_*FF_], g_hl[M_*FF_];
__device__ __align__(128) __half g_qh[M_*D_];
__device__ __align__(128) __half g_kh[M_*D_];
__device__ __align__(128) __half g_bh[(size_t)V_*D_];
__device__ __align__(128) __half g_sh[(size_t)B_*H_*S_*SP_];       // probs (pad=0)
__device__ __align__(128) __half g_vh[(size_t)B_*H_*HD_*SP_];      // V^T (pad=0)

// ======================= helpers =============================================
__device__ __forceinline__ uint32_t smem_u32(const void* p){
    uint32_t a;
    asm("{ .reg .u64 t; cvta.to.shared.u64 t, %1; cvt.u32.u64 %0, t; }" : "=r"(a) : "l"(p));
    return a;
}
__device__ __forceinline__ void split1(float v, __half& h, __half& l){
    h = __float2half(v);
    l = __float2half(v - __half2float(h));
}
__device__ __forceinline__ void ldm_x4(uint32_t* r, uint32_t addr){
    asm volatile("ldmatrix.sync.aligned.m8n8.x4.shared.b16 {%0,%1,%2,%3}, [%4];"
        : "=r"(r[0]), "=r"(r[1]), "=r"(r[2]), "=r"(r[3]) : "r"(addr));
}
#define MMAF16(c, a, b0v, b1v) \
    asm volatile("mma.sync.aligned.m16n8k16.row.col.f32.f16.f16.f32 " \
        "{%0,%1,%2,%3}, {%4,%5,%6,%7}, {%8,%9}, {%0,%1,%2,%3};" \
        : "+f"((c)[0]), "+f"((c)[1]), "+f"((c)[2]), "+f"((c)[3]) \
        : "r"((a)[0]), "r"((a)[1]), "r"((a)[2]), "r"((a)[3]), "r"(b0v), "r"(b1v))
#define CP_COMMIT() asm volatile("cp.async.commit_group;" ::: "memory")

// ======================= smem tile layout ====================================
#define SROW_B   80
#define MAT_B    (128*SROW_B)

__device__ __forceinline__ void cp_tile(const __half* __restrict__ g, int ld,
                                        int row0, int rowmax, int k0,
                                        uint32_t dst, int tid)
{
#pragma unroll
    for (int c = 0; c < 2; c++) {
        int idx = tid + c*256;
        int r = idx >> 2, q = idx & 3;
        int gr = row0 + r;
        int grc = gr < rowmax ? gr : (rowmax - 1);
        const char* src = (const char*)(g + (size_t)grc*ld + k0) + q*16;
        uint32_t d = dst + r*SROW_B + q*16;
        int sz = (gr < rowmax) ? 16 : 0;
        asm volatile("cp.async.cg.shared.global [%0], [%1], 16, %2;"
            :: "r"(d), "l"(src), "r"(sz));
    }
}

// ======================= fp16 mma.sync GEMM ==================================
// SPLIT=false: C = act(alpha * Ah @ Bh^T + bias)        (1 pass, NSTG=4)
// SPLIT=true : C = act(alpha * (Ah+Al) @ Bh^T + bias)   (2 passes, NSTG=3)
// outmode 0: fp32 C | 1: fp16 hi/lo -> Oh,Ol | 2: fp16 hi -> Oh
// outmode 4: merged QKV: c0<512 -> Oh(q), <1024 -> Ol(k), else V^T -> (half*)C
template<bool SPLIT>
__global__ __launch_bounds__(256, 2)
void tmm_kernel(const __half* __restrict__ Ah, const __half* __restrict__ Al, int lda,
                const __half* __restrict__ Bh, int ldb,
                const float* __restrict__ bias,
                float* __restrict__ C,
                __half* __restrict__ Oh, __half* __restrict__ Ol, int ldc,
                int Mv, int Nv, int K,
                long long sAb, long long sAh, long long sBb, long long sBh,
                long long sCb, long long sCh,
                float alpha, int relu, int outmode)
{
    extern __shared__ char sm[];
    const uint32_t sb = smem_u32(sm);
    const int tid  = threadIdx.x;
    const int wid  = tid >> 5;
    const int lane = tid & 31;
    constexpr int NSTG_ = SPLIT ? 3 : 4;
    constexpr int TPS   = SPLIT ? 3 : 2;
    constexpr int STG   = TPS * MAT_B;

    const long long zb = blockIdx.z / H_;
    const long long zh = blockIdx.z % H_;
    Ah += zb*sAb + zh*sAh;  Bh += zb*sBb + zh*sBh;
    if (SPLIT) Al += zb*sAb + zh*sAh;
    const size_t cOff = (size_t)(zb*sCb + zh*sCh);

    const int m0 = blockIdx.y * 128;
    const int n0 = blockIdx.x * 128;
    const int wm = (wid >> 2) * 64;
    const int wn = (wid & 3) * 32;
    const int rem = Nv - n0 - wn;            // valid cols for this warp (may be <=0)

    const uint32_t aoff = (uint32_t)(wm + (lane & 15)) * SROW_B + ((lane >> 4) * 16);
    const uint32_t boff = (uint32_t)(wn + (lane & 7) + ((lane >> 4) * 8)) * SROW_B
                        + (((lane >> 3) & 1) * 16);

    float acc[4][4][4];
#pragma unroll
    for (int i = 0; i < 4; i++)
#pragma unroll
        for (int j = 0; j < 4; j++)
#pragma unroll
            for (int e = 0; e < 4; e++) acc[i][j][e] = 0.f;

    const int NC = K >> 5;

    auto issue = [&](int s){
        uint32_t base = sb + (s % NSTG_) * STG;
        int k0 = s << 5;
        cp_tile(Ah, lda, m0, Mv, k0, base + 0*MAT_B, tid);
        if (SPLIT) cp_tile(Al, lda, m0, Mv, k0, base + 1*MAT_B, tid);
        cp_tile(Bh, ldb, n0, Nv, k0, base + (SPLIT?2:1)*MAT_B, tid);
    };

#pragma unroll
    for (int s = 0; s < NSTG_-1; s++) {
        if (s < NC) issue(s);
        CP_COMMIT();
    }

    for (int kc = 0; kc < NC; kc++) {
        if constexpr (SPLIT) asm volatile("cp.async.wait_group 1;" ::: "memory");
        else                 asm volatile("cp.async.wait_group 2;" ::: "memory");
        __syncthreads();
        const uint32_t base = sb + (kc % NSTG_) * STG;
        const uint32_t aBH = base + 0*MAT_B + aoff;
        const uint32_t aBL = base + 1*MAT_B + aoff;
        const uint32_t bBH = base + (SPLIT?2:1)*MAT_B + boff;

#pragma unroll
        for (int ks = 0; ks < 2; ks++) {
            uint32_t ah[4][4], bh[2][4];
#pragma unroll
            for (int mt = 0; mt < 4; mt++) ldm_x4(ah[mt], aBH + mt*(16*SROW_B) + ks*32);
#pragma unroll
            for (int p = 0; p < 2; p++)
                if (p*16 < rem) ldm_x4(bh[p], bBH + p*(16*SROW_B) + ks*32);
            if constexpr (SPLIT) {
                uint32_t al[4][4];
#pragma unroll
                for (int mt = 0; mt < 4; mt++) ldm_x4(al[mt], aBL + mt*(16*SROW_B) + ks*32);
#pragma unroll
                for (int mt = 0; mt < 4; mt++)
#pragma unroll
                    for (int nt = 0; nt < 4; nt++)
                        if (nt*8 < rem) {
                            uint32_t b0 = bh[nt>>1][(nt&1)*2], b1 = bh[nt>>1][(nt&1)*2+1];
                            MMAF16(acc[mt][nt], ah[mt], b0, b1);
                            MMAF16(acc[mt][nt], al[mt], b0, b1);
                        }
            } else {
#pragma unroll
                for (int mt = 0; mt < 4; mt++)
#pragma unroll
                    for (int nt = 0; nt < 4; nt++)
                        if (nt*8 < rem) {
                            uint32_t b0 = bh[nt>>1][(nt&1)*2], b1 = bh[nt>>1][(nt&1)*2+1];
                            MMAF16(acc[mt][nt], ah[mt], b0, b1);
                        }
            }
        }
        if (kc + NSTG_ - 1 < NC) issue(kc + NSTG_ - 1);
        CP_COMMIT();
    }

    // ---- epilogue ----
    const int gq = lane >> 2;
    const int tg = lane & 3;
#pragma unroll
    for (int mt = 0; mt < 4; mt++) {
#pragma unroll
        for (int half_ = 0; half_ < 2; half_++) {
            int r = m0 + wm + mt*16 + gq + half_*8;
            if (r >= Mv) continue;
#pragma unroll
            for (int nt = 0; nt < 4; nt++) {
                int c0 = n0 + wn + nt*8 + tg*2;
                if (c0 >= Nv) continue;
                float v0 = alpha*acc[mt][nt][half_*2+0];
                float v1 = alpha*acc[mt][nt][half_*2+1];
                if (bias) { v0 += bias[c0]; v1 += bias[c0+1]; }
                if (relu) { v0 = fmaxf(v0, 0.f); v1 = fmaxf(v1, 0.f); }
                if (outmode == 0) {
                    *reinterpret_cast<float2*>(C + cOff + (size_t)r*ldc + c0) = make_float2(v0, v1);
                } else if (outmode == 1) {
                    __half h0,l0,h1,l1;
                    split1(v0,h0,l0); split1(v1,h1,l1);
                    size_t base2 = cOff + (size_t)r*ldc + c0;
                    *reinterpret_cast<__half2*>(Oh + base2) = __half2(h0,h1);
                    *reinterpret_cast<__half2*>(Ol + base2) = __half2(l0,l1);
                } else if (outmode == 2) {
                    size_t base2 = cOff + (size_t)r*ldc + c0;
                    *reinterpret_cast<__half2*>(Oh + base2) =
                        __half2(__float2half(v0), __float2half(v1));
                } else {
                    if (c0 < 1024) {
                        __half2 hv(__float2half(v0), __float2half(v1));
                        if (c0 < 512)
                            *reinterpret_cast<__half2*>(Oh + (size_t)r*D_ + c0) = hv;
                        else
                            *reinterpret_cast<__half2*>(Ol + (size_t)r*D_ + (c0-512)) = hv;
                    } else {
                        __half* Vt = reinterpret_cast<__half*>(C);
                        int b = r / S_, s = r - b*S_;
                        int cc = c0 - 1024;
                        int hi = cc >> 6, di = cc & 63;
                        Vt[(((size_t)b*H_ + hi)*HD_ + di    )*SP_ + s] = __float2half(v0);
                        Vt[(((size_t)b*H_ + hi)*HD_ + di + 1)*SP_ + s] = __float2half(v1);
                    }
                }
            }
        }
    }
}

// ======================= weight transpose -> fp16 ============================
__global__ void wsplit_t(const float* __restrict__ W,
                         __half* __restrict__ oh, int K, int N)
{
    __shared__ float t[32][33];
    int n = blockIdx.x*32 + threadIdx.x;
    int k0 = blockIdx.y*32;
    #pragma unroll
    for (int j = 0; j < 4; j++)
        t[threadIdx.y + j*8][threadIdx.x] = W[(size_t)(k0 + threadIdx.y + j*8)*N + n];
    __syncthreads();
    int k = k0 + threadIdx.x;
    #pragma unroll
    for (int j = 0; j < 4; j++) {
        int nn = blockIdx.x*32 + threadIdx.y + j*8;
        oh[(size_t)nn*K + k] = __float2half(t[threadIdx.x][threadIdx.y + j*8]);
    }
}

// ======================= merged QKV bias =====================================
__global__ void qkv_bias(const float* __restrict__ bq, const float* __restrict__ bk,
                         const float* __restrict__ bv, float* __restrict__ o)
{
    int i = blockIdx.x*256 + threadIdx.x;       // 0..1535
    o[i] = (i < 512) ? bq[i] : (i < 1024 ? bk[i-512] : bv[i-1024]);
}

// ======================= embed + posenc (+ hi/lo split) ======================
__global__ void embed_kernel(const int* __restrict__ tokens,
                             const float* __restrict__ emb,
                             float* __restrict__ x,
                             __half* __restrict__ oh,
                             __half* __restrict__ ol)
{
    int row = blockIdx.x, d = threadIdx.x;
    int s = row % S_;
    int tok = tokens[row];
    int i = d >> 1;
    float dv  = expf(-(float)(2*i) * (9.210340371976184f / (float)D_));
    float arg = (float)s * dv;
    float pe  = (d & 1) ? cosf(arg) : sinf(arg);
    float val = emb[(size_t)tok*D_ + d] + pe;
    size_t idx = (size_t)row*D_ + d;
    x[idx] = val;
    __half h,l; split1(val, h, l); oh[idx]=h; ol[idx]=l;
}

// ======================= scores softmax (fp16 in) -> fp16 probs ==============
__global__ void softmax_split(const __half* __restrict__ sc,
                              __half* __restrict__ oh)
{
    __shared__ float row[S_];
    __shared__ float bm[8], bs[8];
    __shared__ float s_m, s_inv;
    int z = blockIdx.x / S_, r = blockIdx.x % S_;
    const __half* p = sc + (size_t)z*S_*S_ + (size_t)r*S_;
    const int tid = threadIdx.x, lane = tid & 31, wrp = tid >> 5;

    float m = -3.4e38f;
    for (int i = tid; i < S_; i += 256) { float v = __half2float(p[i]); row[i] = v; m = fmaxf(m, v); }
    #pragma unroll
    for (int o = 16; o; o >>= 1) m = fmaxf(m, __shfl_xor_sync(0xffffffffu, m, o));
    if (lane == 0) bm[wrp] = m;
    __syncthreads();
    if (tid == 0) {
        float t = bm[0];
        #pragma unroll
        for (int i = 1; i < 8; i++) t = fmaxf(t, bm[i]);
        s_m = t;
    }
    __syncthreads();
    m = s_m;
    float s = 0.f;
    for (int i = tid; i < S_; i += 256) s += __expf(row[i] - m);
    #pragma unroll
    for (int o = 16; o; o >>= 1) s += __shfl_xor_sync(0xffffffffu, s, o);
    if (lane == 0) bs[wrp] = s;
    __syncthreads();
    if (tid == 0) {
        float t = 0.f;
        #pragma unroll
        for (int i = 0; i < 8; i++) t += bs[i];
        s_inv = 1.0f / t;
    }
    __syncthreads();
    const float mm = s_m, inv = s_inv;
    const size_t ob = (size_t)z*S_*SP_ + (size_t)r*SP_;
    for (int c = tid; c < S_; c += 256)
        oh[ob + c] = __float2half(__expf(row[c] - mm) * inv);
}

// ======================= final V-softmax (smem row, 512 thr) =================
__global__ void softmax_big(float* __restrict__ data)
{
    extern __shared__ float row[];
    float* p = data + (size_t)blockIdx.x * V_;
    const int tid = threadIdx.x, lane = tid & 31, wrp = tid >> 5;
    __shared__ float bm[16], bs[16];
    __shared__ float s_m, s_inv;

    float m = -3.4e38f;
    for (int i = tid; i < V_; i += 512) { float v = p[i]; row[i] = v; m = fmaxf(m, v); }
    #pragma unroll
    for (int o = 16; o; o >>= 1) m = fmaxf(m, __shfl_xor_sync(0xffffffffu, m, o));
    if (lane == 0) bm[wrp] = m;
    __syncthreads();
    if (tid == 0) {
        float t = bm[0];
        #pragma unroll
        for (int i = 1; i < 16; i++) t = fmaxf(t, bm[i]);
        s_m = t;
    }
    __syncthreads();
    m = s_m;
    float s = 0.f;
    for (int i = tid; i < V_; i += 512) s += __expf(row[i] - m);
    #pragma unroll
    for (int o = 16; o; o >>= 1) s += __shfl_xor_sync(0xffffffffu, s, o);
    if (lane == 0) bs[wrp] = s;
    __syncthreads();
    if (tid == 0) {
        float t = 0.f;
        #pragma unroll
        for (int i = 0; i < 16; i++) t += bs[i];
        s_inv = 1.0f / t;
    }
    __syncthreads();
    const float mm = s_m, inv = s_inv;
    for (int i = tid; i < V_; i += 512)
        p[i] = __expf(row[i] - mm) * inv;
}

// ======================= residual add + LayerNorm (+ split) ==================
__global__ void add_ln_kernel(const float* __restrict__ xin,
                              const float* __restrict__ res,
                              const float* __restrict__ g,
                              const float* __restrict__ b,
                              float* __restrict__ xout,
                              __half* __restrict__ oh,
                              __half* __restrict__ ol)
{
    const int row = blockIdx.x, d = threadIdx.x;
    const int lane = d & 31, wrp = d >> 5;
    size_t idx = (size_t)row*D_ + d;
    float y = xin[idx] + res[idx];
    __shared__ float bsum[16], bsq[16];
    __shared__ float s_mu, s_rs;
    float s1 = y, s2 = y*y;
    #pragma unroll
    for (int o = 16; o; o >>= 1) {
        s1 += __shfl_xor_sync(0xffffffffu, s1, o);
        s2 += __shfl_xor_sync(0xffffffffu, s2, o);
    }
    if (lane == 0) { bsum[wrp] = s1; bsq[wrp] = s2; }
    __syncthreads();
    if (d == 0) {
        float a = 0.f, c = 0.f;
        #pragma unroll
        for (int i = 0; i < 16; i++) { a += bsum[i]; c += bsq[i]; }
        float mu = a * (1.0f/D_);
        float var = c * (1.0f/D_) - mu*mu;
        s_mu = mu; s_rs = rsqrtf(var + 1e-5f);
    }
    __syncthreads();
    float val = (y - s_mu) * s_rs * g[d] + b[d];
    xout[idx] = val;
    __half h,l; split1(val, h, l); oh[idx]=h; ol[idx]=l;
}

// ======================= launcher ============================================
#define SMEM_SPLIT  (3*3*MAT_B)   // 92160  -> 2 CTA/SM
#define SMEM_SINGLE (4*2*MAT_B)   // 81920  -> 2 CTA/SM

extern "C" void kernel_launch(void* const* d_in, const int* in_sizes, int n_in,
                              void* d_out, int out_size)
{
    (void)in_sizes; (void)n_in; (void)out_size;
    const int*   tokens = (const int*)  d_in[0];
    const float* emb  = (const float*)d_in[1];
    const float* wq   = (const float*)d_in[2];
    const float* bq   = (const float*)d_in[3];
    const float* wk   = (const float*)d_in[4];
    const float* bk   = (const float*)d_in[5];
    const float* wv   = (const float*)d_in[6];
    const float* bv   = (const float*)d_in[7];
    const float* wo   = (const float*)d_in[8];
    const float* bo   = (const float*)d_in[9];
    const float* ln1g = (const float*)d_in[10];
    const float* ln1b = (const float*)d_in[11];
    const float* w1   = (const float*)d_in[12];
    const float* b1   = (const float*)d_in[13];
    const float* w2   = (const float*)d_in[14];
    const float* b2   = (const float*)d_in[15];
    const float* ln2g = (const float*)d_in[16];
    const float* ln2b = (const float*)d_in[17];
    const float* fcw  = (const float*)d_in[18];
    const float* fcb  = (const float*)d_in[19];
    float* out = (float*)d_out;

    float *x,*t,*qkvb;
    __half *sc,*ah,*al,*hh,*hl,*qh,*kh,*bh,*sh,*vh;
    cudaGetSymbolAddress((void**)&x,  g_x);  cudaGetSymbolAddress((void**)&t,  g_t);
    cudaGetSymbolAddress((void**)&sc, g_sc); cudaGetSymbolAddress((void**)&qkvb, g_qkvb);
    cudaGetSymbolAddress((void**)&ah, g_ah); cudaGetSymbolAddress((void**)&al, g_al);
    cudaGetSymbolAddress((void**)&hh, g_hh); cudaGetSymbolAddress((void**)&hl, g_hl);
    cudaGetSymbolAddress((void**)&qh, g_qh); cudaGetSymbolAddress((void**)&kh, g_kh);
    cudaGetSymbolAddress((void**)&bh, g_bh);
    cudaGetSymbolAddress((void**)&sh, g_sh); cudaGetSymbolAddress((void**)&vh, g_vh);

    cudaFuncSetAttribute(tmm_kernel<true>,  cudaFuncAttributeMaxDynamicSharedMemorySize, SMEM_SPLIT);
    cudaFuncSetAttribute(tmm_kernel<false>, cudaFuncAttributeMaxDynamicSharedMemorySize, SMEM_SINGLE);
    cudaFuncSetAttribute(softmax_big, cudaFuncAttributeMaxDynamicSharedMemorySize, V_*4);

    embed_kernel<<<M_, D_>>>(tokens, emb, x, ah, al);

    const dim3 gQKV(1536/128, (M_+127)/128);
    const dim3 gDD (D_/128,  (M_+127)/128);
    const dim3 gFF (FF_/128, (M_+127)/128);
    const dim3 gSC ((S_+127)/128, (S_+127)/128, B_*H_);
    const dim3 gCX (1, (S_+127)/128, B_*H_);
    const dim3 tb (32, 8);

    for (int l = 0; l < L_; l++) {
        const float* lwq = wq + (size_t)l*D_*D_;
        const float* lwk = wk + (size_t)l*D_*D_;
        const float* lwv = wv + (size_t)l*D_*D_;
        const float* lwo = wo + (size_t)l*D_*D_;
        const float* lw1 = w1 + (size_t)l*D_*FF_;
        const float* lw2 = w2 + (size_t)l*FF_*D_;

        // ---- merged QKV projection (single fp16) ----
        wsplit_t<<<dim3(D_/32, D_/32), tb>>>(lwq, bh,           D_, D_);
        wsplit_t<<<dim3(D_/32, D_/32), tb>>>(lwk, bh +  512*D_, D_, D_);
        wsplit_t<<<dim3(D_/32, D_/32), tb>>>(lwv, bh + 1024*D_, D_, D_);
        qkv_bias<<<6, 256>>>(bq + l*D_, bk + l*D_, bv + l*D_, qkvb);
        tmm_kernel<false><<<gQKV, 256, SMEM_SINGLE>>>(ah, nullptr, D_, bh, D_,
            qkvb, (float*)vh, qh, kh, D_, M_, 1536, D_, 0,0,0,0,0,0, 1.f, 0, 4);

        // ---- scores = QK^T/8 (single, K=64) -> fp16 ----
        tmm_kernel<false><<<gSC, 256, SMEM_SINGLE>>>(qh, nullptr, D_, kh, D_,
            nullptr, nullptr, sc, nullptr, S_, S_, S_, 64,
            (long long)S_*D_, HD_, (long long)S_*D_, HD_,
            (long long)H_*S_*S_, (long long)S_*S_, 0.125f, 0, 2);

        softmax_split<<<B_*H_*S_, 256>>>(sc, sh);

        // ---- ctx = probs @ V^T (single, K=1024 padded) -> fp16 into qh ----
        tmm_kernel<false><<<gCX, 256, SMEM_SINGLE>>>(sh, nullptr, SP_, vh, SP_,
            nullptr, nullptr, qh, nullptr, D_, S_, HD_, SP_,
            (long long)H_*S_*SP_, (long long)S_*SP_,
            (long long)H_*HD_*SP_, (long long)HD_*SP_,
            (long long)S_*D_, HD_, 1.f, 0, 2);

        // ---- output projection (single) ----
        wsplit_t<<<dim3(D_/32, D_/32), tb>>>(lwo, bh, D_, D_);
        tmm_kernel<false><<<gDD, 256, SMEM_SINGLE>>>(qh, nullptr, D_, bh, D_,
            bo + l*D_, t, nullptr, nullptr, D_, M_, D_, D_, 0,0,0,0,0,0, 1.f, 0, 0);

        add_ln_kernel<<<M_, D_>>>(x, t, ln1g + l*D_, ln1b + l*D_, x, ah, al);

        // ---- FFN (2-pass split) ----
        wsplit_t<<<dim3(FF_/32, D_/32), tb>>>(lw1, bh, D_, FF_);
        tmm_kernel<true><<<gFF, 256, SMEM_SPLIT>>>(ah, al, D_, bh, D_,
            b1 + l*FF_, nullptr, hh, hl, FF_, M_, FF_, D_, 0,0,0,0,0,0, 1.f, 1, 1);
        wsplit_t<<<dim3(D_/32, FF_/32), tb>>>(lw2, bh, FF_, D_);
        tmm_kernel<true><<<gDD, 256, SMEM_SPLIT>>>(hh, hl, FF_, bh, FF_,
            b2 + l*D_, t, nullptr, nullptr, D_, M_, D_, FF_, 0,0,0,0,0,0, 1.f, 0, 0);

        add_ln_kernel<<<M_, D_>>>(x, t, ln2g + l*D_, ln2b + l*D_, x, ah, al);
    }

    // ---- logits (2-pass split) + softmax ----
    wsplit_t<<<dim3(V_/32, D_/32), tb>>>(fcw, bh, D_, V_);
    tmm_kernel<true><<<dim3(V_/128, (M_+127)/128), 256, SMEM_SPLIT>>>(ah, al, D_, bh, D_,
        fcb, out, nullptr, nullptr, V_, M_, V_, D_, 0,0,0,0,0,0, 1.f, 0, 0);
    softmax_big<<<M_, 512, V_*4>>>(out);
}

// round 9
// speedup vs baseline: 3.7746x; 1.3595x over previous
#include <cuda_runtime.h>
#include <cuda_fp16.h>
#include <math.h>
#include <stdint.h>

#define B_  4
#define S_  1000
#define D_  512
#define H_  8
#define L_  4
#define V_  32000
#define HD_ 64
#define FF_ 2048
#define M_  (B_*S_)
#define SP_ 1024

// ======================= scratch (device globals, zero-init) =================
__device__ __align__(128) float g_x[M_*D_];
__device__ __align__(128) float g_t[M_*D_];
__device__ __align__(128) __half g_sc[(size_t)B_*H_*S_*S_];        // scores fp16
__device__ __align__(128) float g_qkvb[3*D_];
__device__ __align__(128) __half g_ah[M_*D_];                      // x fp16
__device__ __align__(128) __half g_hh[M_*FF_];                     // FFN mid fp16
__device__ __align__(128) __half g_qh[M_*D_];
__device__ __align__(128) __half g_kh[M_*D_];
__device__ __align__(128) __half g_bh[(size_t)V_*D_];              // W^T fp16
__device__ __align__(128) __half g_sh[(size_t)B_*H_*S_*SP_];       // probs (pad=0)
__device__ __align__(128) __half g_vh[(size_t)B_*H_*HD_*SP_];      // V^T (pad=0)

// ======================= helpers =============================================
__device__ __forceinline__ uint32_t smem_u32(const void* p){
    uint32_t a;
    asm("{ .reg .u64 t; cvta.to.shared.u64 t, %1; cvt.u32.u64 %0, t; }" : "=r"(a) : "l"(p));
    return a;
}
__device__ __forceinline__ void ldm_x4(uint32_t* r, uint32_t addr){
    asm volatile("ldmatrix.sync.aligned.m8n8.x4.shared.b16 {%0,%1,%2,%3}, [%4];"
        : "=r"(r[0]), "=r"(r[1]), "=r"(r[2]), "=r"(r[3]) : "r"(addr));
}
#define MMAF16(c, a, b0v, b1v) \
    asm volatile("mma.sync.aligned.m16n8k16.row.col.f32.f16.f16.f32 " \
        "{%0,%1,%2,%3}, {%4,%5,%6,%7}, {%8,%9}, {%0,%1,%2,%3};" \
        : "+f"((c)[0]), "+f"((c)[1]), "+f"((c)[2]), "+f"((c)[3]) \
        : "r"((a)[0]), "r"((a)[1]), "r"((a)[2]), "r"((a)[3]), "r"(b0v), "r"(b1v))
#define CP_COMMIT() asm volatile("cp.async.commit_group;" ::: "memory")

// ======================= smem tile layout ====================================
#define SROW_B   80
#define MAT_B    (128*SROW_B)
#define NSTG     4
#define SMEM_TMM (NSTG*2*MAT_B)     // 81920 -> 2 CTA/SM

__device__ __forceinline__ void cp_tile(const __half* __restrict__ g, int ld,
                                        int row0, int rowmax, int k0,
                                        uint32_t dst, int tid)
{
#pragma unroll
    for (int c = 0; c < 2; c++) {
        int idx = tid + c*256;
        int r = idx >> 2, q = idx & 3;
        int gr = row0 + r;
        int grc = gr < rowmax ? gr : (rowmax - 1);
        const char* src = (const char*)(g + (size_t)grc*ld + k0) + q*16;
        uint32_t d = dst + r*SROW_B + q*16;
        int sz = (gr < rowmax) ? 16 : 0;
        asm volatile("cp.async.cg.shared.global [%0], [%1], 16, %2;"
            :: "r"(d), "l"(src), "r"(sz));
    }
}

// ======================= fp16 mma.sync GEMM (single pass) ====================
// C = act(alpha * Ah @ Bh^T + bias)
// outmode 0: fp32 C | 2: fp16 -> Oh
// outmode 4: merged QKV: c0<512 -> Oh(q), <1024 -> Ol(k), else V^T -> (half*)C
__global__ __launch_bounds__(256, 2)
void tmm_kernel(const __half* __restrict__ Ah, int lda,
                const __half* __restrict__ Bh, int ldb,
                const float* __restrict__ bias,
                float* __restrict__ C,
                __half* __restrict__ Oh, __half* __restrict__ Ol, int ldc,
                int Mv, int Nv, int K,
                long long sAb, long long sAh, long long sBb, long long sBh,
                long long sCb, long long sCh,
                float alpha, int relu, int outmode)
{
    extern __shared__ char sm[];
    const uint32_t sb = smem_u32(sm);
    const int tid  = threadIdx.x;
    const int wid  = tid >> 5;
    const int lane = tid & 31;

    const long long zb = blockIdx.z / H_;
    const long long zh = blockIdx.z % H_;
    Ah += zb*sAb + zh*sAh;  Bh += zb*sBb + zh*sBh;
    const size_t cOff = (size_t)(zb*sCb + zh*sCh);

    const int m0 = blockIdx.y * 128;
    const int n0 = blockIdx.x * 128;
    const int wm = (wid >> 2) * 64;
    const int wn = (wid & 3) * 32;
    const int rem = Nv - n0 - wn;            // valid cols for this warp

    const uint32_t aoff = (uint32_t)(wm + (lane & 15)) * SROW_B + ((lane >> 4) * 16);
    const uint32_t boff = (uint32_t)(wn + (lane & 7) + ((lane >> 4) * 8)) * SROW_B
                        + (((lane >> 3) & 1) * 16);

    float acc[4][4][4];
#pragma unroll
    for (int i = 0; i < 4; i++)
#pragma unroll
        for (int j = 0; j < 4; j++)
#pragma unroll
            for (int e = 0; e < 4; e++) acc[i][j][e] = 0.f;

    const int NC = K >> 5;

    auto issue = [&](int s){
        uint32_t base = sb + (s % NSTG) * (2*MAT_B);
        int k0 = s << 5;
        cp_tile(Ah, lda, m0, Mv, k0, base + 0*MAT_B, tid);
        cp_tile(Bh, ldb, n0, Nv, k0, base + 1*MAT_B, tid);
    };

#pragma unroll
    for (int s = 0; s < NSTG-1; s++) {
        if (s < NC) issue(s);
        CP_COMMIT();
    }

    for (int kc = 0; kc < NC; kc++) {
        asm volatile("cp.async.wait_group 2;" ::: "memory");
        __syncthreads();
        const uint32_t base = sb + (kc % NSTG) * (2*MAT_B);
        const uint32_t aBH = base + 0*MAT_B + aoff;
        const uint32_t bBH = base + 1*MAT_B + boff;

#pragma unroll
        for (int ks = 0; ks < 2; ks++) {
            uint32_t ah[4][4], bh[2][4];
#pragma unroll
            for (int mt = 0; mt < 4; mt++) ldm_x4(ah[mt], aBH + mt*(16*SROW_B) + ks*32);
#pragma unroll
            for (int p = 0; p < 2; p++)
                if (p*16 < rem) ldm_x4(bh[p], bBH + p*(16*SROW_B) + ks*32);
#pragma unroll
            for (int mt = 0; mt < 4; mt++)
#pragma unroll
                for (int nt = 0; nt < 4; nt++)
                    if (nt*8 < rem) {
                        uint32_t b0 = bh[nt>>1][(nt&1)*2], b1 = bh[nt>>1][(nt&1)*2+1];
                        MMAF16(acc[mt][nt], ah[mt], b0, b1);
                    }
        }
        if (kc + NSTG - 1 < NC) issue(kc + NSTG - 1);
        CP_COMMIT();
    }

    // ---- epilogue ----
    const int gq = lane >> 2;
    const int tg = lane & 3;
#pragma unroll
    for (int mt = 0; mt < 4; mt++) {
#pragma unroll
        for (int half_ = 0; half_ < 2; half_++) {
            int r = m0 + wm + mt*16 + gq + half_*8;
            if (r >= Mv) continue;
#pragma unroll
            for (int nt = 0; nt < 4; nt++) {
                int c0 = n0 + wn + nt*8 + tg*2;
                if (c0 >= Nv) continue;
                float v0 = alpha*acc[mt][nt][half_*2+0];
                float v1 = alpha*acc[mt][nt][half_*2+1];
                if (bias) { v0 += bias[c0]; v1 += bias[c0+1]; }
                if (relu) { v0 = fmaxf(v0, 0.f); v1 = fmaxf(v1, 0.f); }
                if (outmode == 0) {
                    *reinterpret_cast<float2*>(C + cOff + (size_t)r*ldc + c0) = make_float2(v0, v1);
                } else if (outmode == 2) {
                    size_t base2 = cOff + (size_t)r*ldc + c0;
                    *reinterpret_cast<__half2*>(Oh + base2) =
                        __half2(__float2half(v0), __float2half(v1));
                } else {
                    if (c0 < 1024) {
                        __half2 hv(__float2half(v0), __float2half(v1));
                        if (c0 < 512)
                            *reinterpret_cast<__half2*>(Oh + (size_t)r*D_ + c0) = hv;
                        else
                            *reinterpret_cast<__half2*>(Ol + (size_t)r*D_ + (c0-512)) = hv;
                    } else {
                        __half* Vt = reinterpret_cast<__half*>(C);
                        int b = r / S_, s = r - b*S_;
                        int cc = c0 - 1024;
                        int hi = cc >> 6, di = cc & 63;
                        Vt[(((size_t)b*H_ + hi)*HD_ + di    )*SP_ + s] = __float2half(v0);
                        Vt[(((size_t)b*H_ + hi)*HD_ + di + 1)*SP_ + s] = __float2half(v1);
                    }
                }
            }
        }
    }
}

// ======================= weight transpose -> fp16 ============================
__global__ void wsplit_t(const float* __restrict__ W,
                         __half* __restrict__ oh, int K, int N)
{
    __shared__ float t[32][33];
    int n = blockIdx.x*32 + threadIdx.x;
    int k0 = blockIdx.y*32;
    #pragma unroll
    for (int j = 0; j < 4; j++)
        t[threadIdx.y + j*8][threadIdx.x] = W[(size_t)(k0 + threadIdx.y + j*8)*N + n];
    __syncthreads();
    int k = k0 + threadIdx.x;
    #pragma unroll
    for (int j = 0; j < 4; j++) {
        int nn = blockIdx.x*32 + threadIdx.y + j*8;
        oh[(size_t)nn*K + k] = __float2half(t[threadIdx.x][threadIdx.y + j*8]);
    }
}

// ======================= merged QKV bias =====================================
__global__ void qkv_bias(const float* __restrict__ bq, const float* __restrict__ bk,
                         const float* __restrict__ bv, float* __restrict__ o)
{
    int i = blockIdx.x*256 + threadIdx.x;
    o[i] = (i < 512) ? bq[i] : (i < 1024 ? bk[i-512] : bv[i-1024]);
}

// ======================= embed + posenc ======================================
__global__ void embed_kernel(const int* __restrict__ tokens,
                             const float* __restrict__ emb,
                             float* __restrict__ x,
                             __half* __restrict__ oh)
{
    int row = blockIdx.x, d = threadIdx.x;
    int s = row % S_;
    int tok = tokens[row];
    int i = d >> 1;
    float dv  = expf(-(float)(2*i) * (9.210340371976184f / (float)D_));
    float arg = (float)s * dv;
    float pe  = (d & 1) ? cosf(arg) : sinf(arg);
    float val = emb[(size_t)tok*D_ + d] + pe;
    size_t idx = (size_t)row*D_ + d;
    x[idx] = val;
    oh[idx] = __float2half(val);
}

// ======================= scores softmax (fp16 in) -> fp16 probs ==============
__global__ void softmax_split(const __half* __restrict__ sc,
                              __half* __restrict__ oh)
{
    __shared__ float row[S_];
    __shared__ float bm[8], bs[8];
    __shared__ float s_m, s_inv;
    int z = blockIdx.x / S_, r = blockIdx.x % S_;
    const __half* p = sc + (size_t)z*S_*S_ + (size_t)r*S_;
    const int tid = threadIdx.x, lane = tid & 31, wrp = tid >> 5;

    float m = -3.4e38f;
    for (int i = tid; i < S_; i += 256) { float v = __half2float(p[i]); row[i] = v; m = fmaxf(m, v); }
    #pragma unroll
    for (int o = 16; o; o >>= 1) m = fmaxf(m, __shfl_xor_sync(0xffffffffu, m, o));
    if (lane == 0) bm[wrp] = m;
    __syncthreads();
    if (tid == 0) {
        float t = bm[0];
        #pragma unroll
        for (int i = 1; i < 8; i++) t = fmaxf(t, bm[i]);
        s_m = t;
    }
    __syncthreads();
    m = s_m;
    float s = 0.f;
    for (int i = tid; i < S_; i += 256) s += __expf(row[i] - m);
    #pragma unroll
    for (int o = 16; o; o >>= 1) s += __shfl_xor_sync(0xffffffffu, s, o);
    if (lane == 0) bs[wrp] = s;
    __syncthreads();
    if (tid == 0) {
        float t = 0.f;
        #pragma unroll
        for (int i = 0; i < 8; i++) t += bs[i];
        s_inv = 1.0f / t;
    }
    __syncthreads();
    const float mm = s_m, inv = s_inv;
    const size_t ob = (size_t)z*S_*SP_ + (size_t)r*SP_;
    for (int c = tid; c < S_; c += 256)
        oh[ob + c] = __float2half(__expf(row[c] - mm) * inv);
}

// ======================= final V-softmax (smem row, 512 thr) =================
__global__ void softmax_big(float* __restrict__ data)
{
    extern __shared__ float row[];
    float* p = data + (size_t)blockIdx.x * V_;
    const int tid = threadIdx.x, lane = tid & 31, wrp = tid >> 5;
    __shared__ float bm[16], bs[16];
    __shared__ float s_m, s_inv;

    float m = -3.4e38f;
    for (int i = tid; i < V_; i += 512) { float v = p[i]; row[i] = v; m = fmaxf(m, v); }
    #pragma unroll
    for (int o = 16; o; o >>= 1) m = fmaxf(m, __shfl_xor_sync(0xffffffffu, m, o));
    if (lane == 0) bm[wrp] = m;
    __syncthreads();
    if (tid == 0) {
        float t = bm[0];
        #pragma unroll
        for (int i = 1; i < 16; i++) t = fmaxf(t, bm[i]);
        s_m = t;
    }
    __syncthreads();
    m = s_m;
    float s = 0.f;
    for (int i = tid; i < V_; i += 512) s += __expf(row[i] - m);
    #pragma unroll
    for (int o = 16; o; o >>= 1) s += __shfl_xor_sync(0xffffffffu, s, o);
    if (lane == 0) bs[wrp] = s;
    __syncthreads();
    if (tid == 0) {
        float t = 0.f;
        #pragma unroll
        for (int i = 0; i < 16; i++) t += bs[i];
        s_inv = 1.0f / t;
    }
    __syncthreads();
    const float mm = s_m, inv = s_inv;
    for (int i = tid; i < V_; i += 512)
        p[i] = __expf(row[i] - mm) * inv;
}

// ======================= residual add + LayerNorm ============================
__global__ void add_ln_kernel(const float* __restrict__ xin,
                              const float* __restrict__ res,
                              const float* __restrict__ g,
                              const float* __restrict__ b,
                              float* __restrict__ xout,
                              __half* __restrict__ oh)
{
    const int row = blockIdx.x, d = threadIdx.x;
    const int lane = d & 31, wrp = d >> 5;
    size_t idx = (size_t)row*D_ + d;
    float y = xin[idx] + res[idx];
    __shared__ float bsum[16], bsq[16];
    __shared__ float s_mu, s_rs;
    float s1 = y, s2 = y*y;
    #pragma unroll
    for (int o = 16; o; o >>= 1) {
        s1 += __shfl_xor_sync(0xffffffffu, s1, o);
        s2 += __shfl_xor_sync(0xffffffffu, s2, o);
    }
    if (lane == 0) { bsum[wrp] = s1; bsq[wrp] = s2; }
    __syncthreads();
    if (d == 0) {
        float a = 0.f, c = 0.f;
        #pragma unroll
        for (int i = 0; i < 16; i++) { a += bsum[i]; c += bsq[i]; }
        float mu = a * (1.0f/D_);
        float var = c * (1.0f/D_) - mu*mu;
        s_mu = mu; s_rs = rsqrtf(var + 1e-5f);
    }
    __syncthreads();
    float val = (y - s_mu) * s_rs * g[d] + b[d];
    xout[idx] = val;
    oh[idx] = __float2half(val);
}

// ======================= launcher ============================================
extern "C" void kernel_launch(void* const* d_in, const int* in_sizes, int n_in,
                              void* d_out, int out_size)
{
    (void)in_sizes; (void)n_in; (void)out_size;
    const int*   tokens = (const int*)  d_in[0];
    const float* emb  = (const float*)d_in[1];
    const float* wq   = (const float*)d_in[2];
    const float* bq   = (const float*)d_in[3];
    const float* wk   = (const float*)d_in[4];
    const float* bk   = (const float*)d_in[5];
    const float* wv   = (const float*)d_in[6];
    const float* bv   = (const float*)d_in[7];
    const float* wo   = (const float*)d_in[8];
    const float* bo   = (const float*)d_in[9];
    const float* ln1g = (const float*)d_in[10];
    const float* ln1b = (const float*)d_in[11];
    const float* w1   = (const float*)d_in[12];
    const float* b1   = (const float*)d_in[13];
    const float* w2   = (const float*)d_in[14];
    const float* b2   = (const float*)d_in[15];
    const float* ln2g = (const float*)d_in[16];
    const float* ln2b = (const float*)d_in[17];
    const float* fcw  = (const float*)d_in[18];
    const float* fcb  = (const float*)d_in[19];
    float* out = (float*)d_out;

    float *x,*t,*qkvb;
    __half *sc,*ah,*hh,*qh,*kh,*bh,*sh,*vh;
    cudaGetSymbolAddress((void**)&x,  g_x);  cudaGetSymbolAddress((void**)&t,  g_t);
    cudaGetSymbolAddress((void**)&sc, g_sc); cudaGetSymbolAddress((void**)&qkvb, g_qkvb);
    cudaGetSymbolAddress((void**)&ah, g_ah); cudaGetSymbolAddress((void**)&hh, g_hh);
    cudaGetSymbolAddress((void**)&qh, g_qh); cudaGetSymbolAddress((void**)&kh, g_kh);
    cudaGetSymbolAddress((void**)&bh, g_bh);
    cudaGetSymbolAddress((void**)&sh, g_sh); cudaGetSymbolAddress((void**)&vh, g_vh);

    cudaFuncSetAttribute(tmm_kernel, cudaFuncAttributeMaxDynamicSharedMemorySize, SMEM_TMM);
    cudaFuncSetAttribute(softmax_big, cudaFuncAttributeMaxDynamicSharedMemorySize, V_*4);

    embed_kernel<<<M_, D_>>>(tokens, emb, x, ah);

    const dim3 gQKV(1536/128, (M_+127)/128);
    const dim3 gDD (D_/128,  (M_+127)/128);
    const dim3 gFF (FF_/128, (M_+127)/128);
    const dim3 gSC ((S_+127)/128, (S_+127)/128, B_*H_);
    const dim3 gCX (1, (S_+127)/128, B_*H_);
    const dim3 tb (32, 8);

    for (int l = 0; l < L_; l++) {
        const float* lwq = wq + (size_t)l*D_*D_;
        const float* lwk = wk + (size_t)l*D_*D_;
        const float* lwv = wv + (size_t)l*D_*D_;
        const float* lwo = wo + (size_t)l*D_*D_;
        const float* lw1 = w1 + (size_t)l*D_*FF_;
        const float* lw2 = w2 + (size_t)l*FF_*D_;

        // ---- merged QKV projection ----
        qkv_bias<<<6, 256>>>(bq + l*D_, bk + l*D_, bv + l*D_, qkvb);
        wsplit_t<<<dim3(D_/32, D_/32), tb>>>(lwq, bh,           D_, D_);
        wsplit_t<<<dim3(D_/32, D_/32), tb>>>(lwk, bh +  512*D_, D_, D_);
        wsplit_t<<<dim3(D_/32, D_/32), tb>>>(lwv, bh + 1024*D_, D_, D_);
        tmm_kernel<<<gQKV, 256, SMEM_TMM>>>(ah, D_, bh, D_,
            qkvb, (float*)vh, qh, kh, D_, M_, 1536, D_, 0,0,0,0,0,0, 1.f, 0, 4);

        // ---- scores = QK^T/8 (K=64) -> fp16 ----
        tmm_kernel<<<gSC, 256, SMEM_TMM>>>(qh, D_, kh, D_,
            nullptr, nullptr, sc, nullptr, S_, S_, S_, 64,
            (long long)S_*D_, HD_, (long long)S_*D_, HD_,
            (long long)H_*S_*S_, (long long)S_*S_, 0.125f, 0, 2);

        softmax_split<<<B_*H_*S_, 256>>>(sc, sh);

        // ---- ctx = probs @ V^T (K=1024 padded) -> fp16 into qh ----
        tmm_kernel<<<gCX, 256, SMEM_TMM>>>(sh, SP_, vh, SP_,
            nullptr, nullptr, qh, nullptr, D_, S_, HD_, SP_,
            (long long)H_*S_*SP_, (long long)S_*SP_,
            (long long)H_*HD_*SP_, (long long)HD_*SP_,
            (long long)S_*D_, HD_, 1.f, 0, 2);

        // ---- output projection ----
        wsplit_t<<<dim3(D_/32, D_/32), tb>>>(lwo, bh, D_, D_);
        tmm_kernel<<<gDD, 256, SMEM_TMM>>>(qh, D_, bh, D_,
            bo + l*D_, t, nullptr, nullptr, D_, M_, D_, D_, 0,0,0,0,0,0, 1.f, 0, 0);

        add_ln_kernel<<<M_, D_>>>(x, t, ln1g + l*D_, ln1b + l*D_, x, ah);

        // ---- FFN (single pass) ----
        wsplit_t<<<dim3(FF_/32, D_/32), tb>>>(lw1, bh, D_, FF_);
        tmm_kernel<<<gFF, 256, SMEM_TMM>>>(ah, D_, bh, D_,
            b1 + l*FF_, nullptr, hh, nullptr, FF_, M_, FF_, D_, 0,0,0,0,0,0, 1.f, 1, 2);
        wsplit_t<<<dim3(D_/32, FF_/32), tb>>>(lw2, bh, FF_, D_);
        tmm_kernel<<<gDD, 256, SMEM_TMM>>>(hh, FF_, bh, FF_,
            b2 + l*D_, t, nullptr, nullptr, D_, M_, D_, FF_, 0,0,0,0,0,0, 1.f, 0, 0);

        add_ln_kernel<<<M_, D_>>>(x, t, ln2g + l*D_, ln2b + l*D_, x, ah);
    }

    // ---- logits (single pass) + softmax ----
    wsplit_t<<<dim3(V_/32, D_/32), tb>>>(fcw, bh, D_, V_);
    tmm_kernel<<<dim3(V_/128, (M_+127)/128), 256, SMEM_TMM>>>(ah, D_, bh, D_,
        fcb, out, nullptr, nullptr, V_, M_, V_, D_, 0,0,0,0,0,0, 1.f, 0, 0);
    softmax_big<<<M_, 512, V_*4>>>(out);
}